// round 15
// baseline (speedup 1.0000x reference)
#include <cuda_runtime.h>
#include <cuda_bf16.h>
#include <cstdint>

#define CL   1024
#define CS   1024
#define CB   8
#define CE   512
#define CH   8
#define CDH  64
#define CBH  64
#define CM   8192
#define CK   512
#define WSZ  (CE * CK)

// ---------------- device scratch ----------------
__device__ __align__(128) float g_qh [CBH * CL * CDH];
__device__ __align__(128) float g_k1h[CBH * CS * CDH];
__device__ __align__(128) float g_k2h[CBH * CS * CDH];
__device__ __align__(128) float g_vh [CBH * CS * CDH];
__device__ __align__(128) float g_v2 [CBH * CS * CDH];
__device__ __align__(128) float g_ll [CBH * CL];
__device__ __align__(128) float g_vv [CBH * CS];
__device__ __align__(128) float g_aa [CBH * CS];
__device__ __align__(128) float g_va [CBH * CS];
// bf16 hi/lo operand caches
__device__ __align__(128) __nv_bfloat16 g_k1hb[CBH * CS * CDH];
__device__ __align__(128) __nv_bfloat16 g_k1lb[CBH * CS * CDH];
__device__ __align__(128) __nv_bfloat16 g_k2hb[CBH * CS * CDH];
__device__ __align__(128) __nv_bfloat16 g_k2lb[CBH * CS * CDH];
__device__ __align__(128) __nv_bfloat16 g_vthb[CBH * CDH * CS];   // [bh][d][s]
__device__ __align__(128) __nv_bfloat16 g_vtlb[CBH * CDH * CS];
// pre-split GEMM operands
__device__ __align__(128) __nv_bfloat16 g_qryh[CM * CK];
__device__ __align__(128) __nv_bfloat16 g_qryl[CM * CK];
__device__ __align__(128) __nv_bfloat16 g_m1h [CM * CK];
__device__ __align__(128) __nv_bfloat16 g_m1l [CM * CK];
__device__ __align__(128) __nv_bfloat16 g_m2h [CM * CK];
__device__ __align__(128) __nv_bfloat16 g_m2l [CM * CK];
__device__ __align__(128) __nv_bfloat16 g_wh  [8 * WSZ];
__device__ __align__(128) __nv_bfloat16 g_wl  [8 * WSZ];
__device__ __align__(128) __nv_bfloat16 g_aoh [CM * CE];
__device__ __align__(128) __nv_bfloat16 g_aol [CM * CE];

// ---------------- MUFU-free math ----------------
__device__ __forceinline__ float fexp(float x) {
    float t = x * 1.4426950408889634f;
    t = fminf(fmaxf(t, -126.0f), 126.0f);
    int i = __float2int_rn(t);
    float u = (t - (float)i) * 0.6931471805599453f;
    float p = 1.3888889e-3f;
    p = fmaf(p, u, 8.3333333e-3f);
    p = fmaf(p, u, 4.1666667e-2f);
    p = fmaf(p, u, 1.6666667e-1f);
    p = fmaf(p, u, 0.5f);
    p = fmaf(p, u, 1.0f);
    p = fmaf(p, u, 1.0f);
    return p * __int_as_float((i + 127) << 23);
}
__device__ __forceinline__ float frcp_pos(float x) {
    float y = __int_as_float(0x7EF127EAu - __float_as_int(x));
    y = y * (2.0f - x * y);
    y = y * (2.0f - x * y);
    y = y * (2.0f - x * y);
    return y;
}
// p = exp(-sqrt(max(det,1e-8))) — fused, MUFU-free, scores are always <= 0
__device__ __forceinline__ float pexp_negsqrt(float det) {
    det = fmaxf(det, 1e-8f);
    float y = __int_as_float(0x5f3759df - (__float_as_int(det) >> 1));
    y = y * fmaf(-0.5f * det, y * y, 1.5f);
    y = y * fmaf(-0.5f * det, y * y, 1.5f);
    float s = det * y;                                  // sqrt(det)
    float t = fmaxf(s * -1.4426950408889634f, -126.0f); // always <= 0
    int i = __float2int_rn(t);
    float u = (t - (float)i) * 0.6931471805599453f;
    float p = 8.3333333e-3f;
    p = fmaf(p, u, 4.1666667e-2f);
    p = fmaf(p, u, 1.6666667e-1f);
    p = fmaf(p, u, 0.5f);
    p = fmaf(p, u, 1.0f);
    p = fmaf(p, u, 1.0f);
    return p * __int_as_float((i + 127) << 23);
}

// ---------------- mma.sync bf16 helper ----------------
__device__ __forceinline__ void mma16816(float* c,
    uint32_t a0, uint32_t a1, uint32_t a2, uint32_t a3,
    uint32_t b0, uint32_t b1)
{
    asm volatile(
        "mma.sync.aligned.m16n8k16.row.col.f32.bf16.bf16.f32 "
        "{%0,%1,%2,%3},{%4,%5,%6,%7},{%8,%9},{%0,%1,%2,%3};"
        : "+f"(c[0]), "+f"(c[1]), "+f"(c[2]), "+f"(c[3])
        : "r"(a0), "r"(a1), "r"(a2), "r"(a3), "r"(b0), "r"(b1));
}

#define GP 72
#define TSZ (128 * GP)
__device__ __forceinline__ uint32_t pkbf(__nv_bfloat16 a, __nv_bfloat16 b) {
    __nv_bfloat162 t(a, b);
    return *reinterpret_cast<uint32_t*>(&t);
}
__device__ __forceinline__ uint32_t pk_hi(float x, float y) {
    return pkbf(__float2bfloat16(x), __float2bfloat16(y));
}
__device__ __forceinline__ uint32_t pk_lo(float x, float y) {
    __nv_bfloat16 hx = __float2bfloat16(x), hy = __float2bfloat16(y);
    return pkbf(__float2bfloat16(x - __bfloat162float(hx)),
                __float2bfloat16(y - __bfloat162float(hy)));
}
__device__ __forceinline__ uint32_t smem_u32(const void* p) {
    uint32_t a;
    asm("{ .reg .u64 t; cvta.to.shared.u64 t, %1; cvt.u32.u64 %0, t; }" : "=r"(a) : "l"(p));
    return a;
}
__device__ __forceinline__ void cpa16(uint32_t dst, const void* src) {
    asm volatile("cp.async.cg.shared.global [%0], [%1], 16;" :: "r"(dst), "l"(src));
}

// ---------------- prep: fp32 -> hi/lo bf16 ----------------
__global__ void __launch_bounds__(256)
prep_act(const float* __restrict__ q, const float* __restrict__ m1,
         const float* __restrict__ m2)
{
    const int z = blockIdx.z;
    const float* src = (z == 0) ? q : (z == 1) ? m1 : m2;
    __nv_bfloat16* H = (z == 0) ? g_qryh : (z == 1) ? g_m1h : g_m2h;
    __nv_bfloat16* L = (z == 0) ? g_qryl : (z == 1) ? g_m1l : g_m2l;
    size_t i4 = (size_t)blockIdx.x * 256 + threadIdx.x;
    float4 x = ((const float4*)src)[i4];
    ((uint2*)H)[i4] = make_uint2(pk_hi(x.x, x.y), pk_hi(x.z, x.w));
    ((uint2*)L)[i4] = make_uint2(pk_lo(x.x, x.y), pk_lo(x.z, x.w));
}

__global__ void __launch_bounds__(256)
prep_w(const float* __restrict__ w0, const float* __restrict__ w1,
       const float* __restrict__ w2, const float* __restrict__ w3,
       const float* __restrict__ w4, const float* __restrict__ w5,
       const float* __restrict__ w6, const float* __restrict__ w7)
{
    const int z = blockIdx.z;
    const float* src;
    switch (z) {
        case 0: src = w0; break; case 1: src = w1; break;
        case 2: src = w2; break; case 3: src = w3; break;
        case 4: src = w4; break; case 5: src = w5; break;
        case 6: src = w6; break; default: src = w7; break;
    }
    size_t i4 = (size_t)blockIdx.x * 256 + threadIdx.x;
    float4 x = ((const float4*)src)[i4];
    ((uint2*)(g_wh + (size_t)z * WSZ))[i4] = make_uint2(pk_hi(x.x, x.y), pk_hi(x.z, x.w));
    ((uint2*)(g_wl + (size_t)z * WSZ))[i4] = make_uint2(pk_lo(x.x, x.y), pk_lo(x.z, x.w));
}

// =====================================================================
// proj3_cp: q/k1/k2 projections (unchanged)
// =====================================================================
#define PJ_STAGE (4 * TSZ)
#define PJ_SMEM_B (2 * PJ_STAGE * 2)

__global__ void __launch_bounds__(256)
proj3_cp(const float* __restrict__ bq, const float* __restrict__ bk1,
         const float* __restrict__ bk2)
{
    extern __shared__ __nv_bfloat16 fs[];
    const uint32_t sbs = smem_u32(fs);
    const int z = blockIdx.z;
    const __nv_bfloat16* Ah_g = (z == 0) ? g_qryh : (z == 1) ? g_m1h : g_m2h;
    const __nv_bfloat16* Al_g = (z == 0) ? g_qryl : (z == 1) ? g_m1l : g_m2l;
    const __nv_bfloat16* Wh_g = g_wh + (size_t)z * WSZ;
    const __nv_bfloat16* Wl_g = g_wl + (size_t)z * WSZ;
    const float* bias = (z == 0) ? bq : (z == 1) ? bk1 : bk2;
    float* C = (z == 0) ? g_qh : (z == 1) ? g_k1h : g_k2h;
    __nv_bfloat16* CHo = (z == 1) ? g_k1hb : g_k2hb;
    __nv_bfloat16* CLo = (z == 1) ? g_k1lb : g_k2lb;

    const int tid = threadIdx.x;
    const int wid = tid >> 5, lane = tid & 31;
    const int wm = wid >> 2, wn = wid & 3;
    const int m0 = blockIdx.x * 128;
    const int n0 = blockIdx.y * 128;
    const int lq = lane >> 2;
    const int lk = (lane & 3) * 2;

    auto issue = [&](int buf, int k0) {
        const uint32_t dbase = sbs + (uint32_t)buf * (PJ_STAGE * 2);
#pragma unroll
        for (int t = 0; t < 16; t++) {
            int cid = tid + t * 256;
            int tile = cid >> 10;
            int r = (cid >> 3) & 127;
            int c = cid & 7;
            const __nv_bfloat16* src;
            if (tile == 0)      src = Ah_g + (size_t)(m0 + r) * CK + k0 + c * 8;
            else if (tile == 1) src = Al_g + (size_t)(m0 + r) * CK + k0 + c * 8;
            else if (tile == 2) src = Wh_g + (size_t)(n0 + r) * CK + k0 + c * 8;
            else                src = Wl_g + (size_t)(n0 + r) * CK + k0 + c * 8;
            cpa16(dbase + (uint32_t)(tile * TSZ + r * GP + c * 8) * 2, src);
        }
        asm volatile("cp.async.commit_group;");
    };

    float acc[4][4][4];
#pragma unroll
    for (int a = 0; a < 4; a++)
#pragma unroll
        for (int b = 0; b < 4; b++)
#pragma unroll
            for (int c = 0; c < 4; c++) acc[a][b][c] = 0.f;

    issue(0, 0);
    for (int blk = 0; blk < 8; blk++) {
        const int buf = blk & 1;
        if (blk < 7) issue(buf ^ 1, (blk + 1) * 64);
        if (blk < 7) asm volatile("cp.async.wait_group 1;");
        else         asm volatile("cp.async.wait_group 0;");
        __syncthreads();

        const __nv_bfloat16* Ah = fs + buf * PJ_STAGE;
        const __nv_bfloat16* Al = Ah + TSZ;
        const __nv_bfloat16* Wh = Ah + 2 * TSZ;
        const __nv_bfloat16* Wl = Ah + 3 * TSZ;

#pragma unroll
        for (int ks = 0; ks < 4; ks++) {
            uint32_t ah[4][4], al[4][4];
#pragma unroll
            for (int mt = 0; mt < 4; mt++) {
                const __nv_bfloat16* ar = Ah + (wm * 64 + mt * 16 + lq) * GP + ks * 16 + lk;
                ah[mt][0] = *(const uint32_t*)ar;
                ah[mt][1] = *(const uint32_t*)(ar + 8 * GP);
                ah[mt][2] = *(const uint32_t*)(ar + 8);
                ah[mt][3] = *(const uint32_t*)(ar + 8 * GP + 8);
                const __nv_bfloat16* al_ = Al + (wm * 64 + mt * 16 + lq) * GP + ks * 16 + lk;
                al[mt][0] = *(const uint32_t*)al_;
                al[mt][1] = *(const uint32_t*)(al_ + 8 * GP);
                al[mt][2] = *(const uint32_t*)(al_ + 8);
                al[mt][3] = *(const uint32_t*)(al_ + 8 * GP + 8);
            }
#pragma unroll
            for (int nt = 0; nt < 4; nt++) {
                const __nv_bfloat16* bh = Wh + (wn * 32 + nt * 8 + lq) * GP + ks * 16 + lk;
                uint32_t bh0 = *(const uint32_t*)bh;
                uint32_t bh1 = *(const uint32_t*)(bh + 8);
                const __nv_bfloat16* bl = Wl + (wn * 32 + nt * 8 + lq) * GP + ks * 16 + lk;
                uint32_t bl0 = *(const uint32_t*)bl;
                uint32_t bl1 = *(const uint32_t*)(bl + 8);
#pragma unroll
                for (int mt = 0; mt < 4; mt++) {
                    mma16816(acc[mt][nt], ah[mt][0], ah[mt][1], ah[mt][2], ah[mt][3], bh0, bh1);
                    mma16816(acc[mt][nt], ah[mt][0], ah[mt][1], ah[mt][2], ah[mt][3], bl0, bl1);
                    mma16816(acc[mt][nt], al[mt][0], al[mt][1], al[mt][2], al[mt][3], bh0, bh1);
                }
            }
        }
        __syncthreads();
    }

    const float scale = (z == 0) ? 0.125f : 1.0f;
#pragma unroll
    for (int mt = 0; mt < 4; mt++) {
#pragma unroll
        for (int nt = 0; nt < 4; nt++) {
            int row = m0 + wm * 64 + mt * 16 + lq;
            int col = n0 + wn * 32 + nt * 8 + lk;
            float b0 = bias[col], b1 = bias[col + 1];
            int h = col >> 6, d = col & 63;
#pragma unroll
            for (int half = 0; half < 2; half++) {
                int r = row + half * 8;
                int t = r >> 3, bi = r & 7;
                float2 v;
                v.x = (acc[mt][nt][half * 2 + 0] + b0) * scale;
                v.y = (acc[mt][nt][half * 2 + 1] + b1) * scale;
                size_t off = ((size_t)(bi * 8 + h) * 1024 + t) * 64 + d;
                *(float2*)(C + off) = v;
                if (z >= 1) {
                    *(uint32_t*)(CHo + off) = pk_hi(v.x, v.y);
                    *(uint32_t*)(CLo + off) = pk_lo(v.x, v.y);
                }
            }
        }
    }
}

// =====================================================================
// projvg_cp: gated value projection, grid.z = modality (unchanged)
// =====================================================================
#define VG_STAGE (6 * TSZ)
#define VG_SMEM_B (2 * VG_STAGE * 2)

__global__ void __launch_bounds__(256)
projvg_cp(const float* __restrict__ bv1, const float* __restrict__ bg1,
          const float* __restrict__ bv2, const float* __restrict__ bg2)
{
    extern __shared__ __nv_bfloat16 fs[];
    const uint32_t sbs = smem_u32(fs);
    const int mod = blockIdx.z;
    const __nv_bfloat16* Ah_g = mod ? g_m2h : g_m1h;
    const __nv_bfloat16* Al_g = mod ? g_m2l : g_m1l;
    const __nv_bfloat16* Vh_g = g_wh + (size_t)(3 + mod) * WSZ;
    const __nv_bfloat16* Vl_g = g_wl + (size_t)(3 + mod) * WSZ;
    const __nv_bfloat16* Gh_g = g_wh + (size_t)(5 + mod) * WSZ;
    const __nv_bfloat16* Gl_g = g_wl + (size_t)(5 + mod) * WSZ;
    const float* bv = mod ? bv2 : bv1;
    const float* bg = mod ? bg2 : bg1;
    float* Cdst = mod ? g_v2 : g_vh;

    const int tid = threadIdx.x;
    const int wid = tid >> 5, lane = tid & 31;
    const int wm = wid >> 2, wn = wid & 3;
    const int m0 = blockIdx.x * 128;
    const int n0 = blockIdx.y * 128;
    const int lq = lane >> 2;
    const int lk = (lane & 3) * 2;

    auto issue = [&](int buf, int k0) {
        const uint32_t dbase = sbs + (uint32_t)buf * (VG_STAGE * 2);
#pragma unroll
        for (int t = 0; t < 24; t++) {
            int cid = tid + t * 256;
            int tile = cid >> 10;
            int r = (cid >> 3) & 127;
            int c = cid & 7;
            const __nv_bfloat16* src;
            if (tile == 0)      src = Ah_g + (size_t)(m0 + r) * CK + k0 + c * 8;
            else if (tile == 1) src = Al_g + (size_t)(m0 + r) * CK + k0 + c * 8;
            else if (tile == 2) src = Vh_g + (size_t)(n0 + r) * CK + k0 + c * 8;
            else if (tile == 3) src = Vl_g + (size_t)(n0 + r) * CK + k0 + c * 8;
            else if (tile == 4) src = Gh_g + (size_t)(n0 + r) * CK + k0 + c * 8;
            else                src = Gl_g + (size_t)(n0 + r) * CK + k0 + c * 8;
            cpa16(dbase + (uint32_t)(tile * TSZ + r * GP + c * 8) * 2, src);
        }
        asm volatile("cp.async.commit_group;");
    };

    float av_[4][4][4], ag_[4][4][4];
#pragma unroll
    for (int a = 0; a < 4; a++)
#pragma unroll
        for (int b = 0; b < 4; b++)
#pragma unroll
            for (int c = 0; c < 4; c++) { av_[a][b][c] = 0.f; ag_[a][b][c] = 0.f; }

    issue(0, 0);
    for (int blk = 0; blk < 8; blk++) {
        const int buf = blk & 1;
        if (blk < 7) issue(buf ^ 1, (blk + 1) * 64);
        if (blk < 7) asm volatile("cp.async.wait_group 1;");
        else         asm volatile("cp.async.wait_group 0;");
        __syncthreads();

        const __nv_bfloat16* Ah = fs + buf * VG_STAGE;
        const __nv_bfloat16* Al = Ah + TSZ;
        const __nv_bfloat16* Vh = Ah + 2 * TSZ;
        const __nv_bfloat16* Vl = Ah + 3 * TSZ;
        const __nv_bfloat16* Gh = Ah + 4 * TSZ;
        const __nv_bfloat16* Gl = Ah + 5 * TSZ;

#pragma unroll
        for (int ks = 0; ks < 4; ks++) {
            uint32_t ah[4][4], al[4][4];
#pragma unroll
            for (int mt = 0; mt < 4; mt++) {
                const __nv_bfloat16* ar = Ah + (wm * 64 + mt * 16 + lq) * GP + ks * 16 + lk;
                ah[mt][0] = *(const uint32_t*)ar;
                ah[mt][1] = *(const uint32_t*)(ar + 8 * GP);
                ah[mt][2] = *(const uint32_t*)(ar + 8);
                ah[mt][3] = *(const uint32_t*)(ar + 8 * GP + 8);
                const __nv_bfloat16* al_ = Al + (wm * 64 + mt * 16 + lq) * GP + ks * 16 + lk;
                al[mt][0] = *(const uint32_t*)al_;
                al[mt][1] = *(const uint32_t*)(al_ + 8 * GP);
                al[mt][2] = *(const uint32_t*)(al_ + 8);
                al[mt][3] = *(const uint32_t*)(al_ + 8 * GP + 8);
            }
#pragma unroll
            for (int nt = 0; nt < 4; nt++) {
                const __nv_bfloat16* vh = Vh + (wn * 32 + nt * 8 + lq) * GP + ks * 16 + lk;
                uint32_t vh0 = *(const uint32_t*)vh;
                uint32_t vh1 = *(const uint32_t*)(vh + 8);
                const __nv_bfloat16* vl = Vl + (wn * 32 + nt * 8 + lq) * GP + ks * 16 + lk;
                uint32_t vl0 = *(const uint32_t*)vl;
                uint32_t vl1 = *(const uint32_t*)(vl + 8);
                const __nv_bfloat16* gh = Gh + (wn * 32 + nt * 8 + lq) * GP + ks * 16 + lk;
                uint32_t gh0 = *(const uint32_t*)gh;
                uint32_t gh1 = *(const uint32_t*)(gh + 8);
                const __nv_bfloat16* gl = Gl + (wn * 32 + nt * 8 + lq) * GP + ks * 16 + lk;
                uint32_t gl0 = *(const uint32_t*)gl;
                uint32_t gl1 = *(const uint32_t*)(gl + 8);
#pragma unroll
                for (int mt = 0; mt < 4; mt++) {
                    mma16816(av_[mt][nt], ah[mt][0], ah[mt][1], ah[mt][2], ah[mt][3], vh0, vh1);
                    mma16816(av_[mt][nt], ah[mt][0], ah[mt][1], ah[mt][2], ah[mt][3], vl0, vl1);
                    mma16816(av_[mt][nt], al[mt][0], al[mt][1], al[mt][2], al[mt][3], vh0, vh1);
                    mma16816(ag_[mt][nt], ah[mt][0], ah[mt][1], ah[mt][2], ah[mt][3], gh0, gh1);
                    mma16816(ag_[mt][nt], ah[mt][0], ah[mt][1], ah[mt][2], ah[mt][3], gl0, gl1);
                    mma16816(ag_[mt][nt], al[mt][0], al[mt][1], al[mt][2], al[mt][3], gh0, gh1);
                }
            }
        }
        __syncthreads();
    }

#pragma unroll
    for (int mt = 0; mt < 4; mt++) {
#pragma unroll
        for (int nt = 0; nt < 4; nt++) {
            int row = m0 + wm * 64 + mt * 16 + lq;
            int col = n0 + wn * 32 + nt * 8 + lk;
            float bv0 = bv[col], bv1_ = bv[col + 1];
            float bg0 = bg[col], bg1_ = bg[col + 1];
            int h = col >> 6, d = col & 63;
#pragma unroll
            for (int half = 0; half < 2; half++) {
                int r = row + half * 8;
                int t = r >> 3, bi = r & 7;
                float vx0 = av_[mt][nt][half * 2 + 0] + bv0;
                float vx1 = av_[mt][nt][half * 2 + 1] + bv1_;
                float gx0 = ag_[mt][nt][half * 2 + 0] + bg0;
                float gx1 = ag_[mt][nt][half * 2 + 1] + bg1_;
                float2 v;
                v.x = vx0 * frcp_pos(1.0f + fexp(-gx0));
                v.y = vx1 * frcp_pos(1.0f + fexp(-gx1));
                *(float2*)(Cdst + ((size_t)(bi * 8 + h) * 1024 + t) * 64 + d) = v;
            }
        }
    }
}

// =====================================================================
// proj_out_cp: out = ao @ Wo^T + bo (unchanged)
// =====================================================================
__global__ void __launch_bounds__(256)
proj_out_cp(const float* __restrict__ bias, float* __restrict__ C)
{
    extern __shared__ __nv_bfloat16 fs[];
    const uint32_t sbs = smem_u32(fs);
    const __nv_bfloat16* Wh_g = g_wh + (size_t)7 * WSZ;
    const __nv_bfloat16* Wl_g = g_wl + (size_t)7 * WSZ;

    const int tid = threadIdx.x;
    const int wid = tid >> 5, lane = tid & 31;
    const int wm = wid >> 2, wn = wid & 3;
    const int m0 = blockIdx.x * 128;
    const int n0 = blockIdx.y * 128;
    const int lq = lane >> 2;
    const int lk = (lane & 3) * 2;

    auto issue = [&](int buf, int k0) {
        const uint32_t dbase = sbs + (uint32_t)buf * (PJ_STAGE * 2);
#pragma unroll
        for (int t = 0; t < 16; t++) {
            int cid = tid + t * 256;
            int tile = cid >> 10;
            int r = (cid >> 3) & 127;
            int c = cid & 7;
            const __nv_bfloat16* src;
            if (tile == 0)      src = g_aoh + (size_t)(m0 + r) * CE + k0 + c * 8;
            else if (tile == 1) src = g_aol + (size_t)(m0 + r) * CE + k0 + c * 8;
            else if (tile == 2) src = Wh_g + (size_t)(n0 + r) * CK + k0 + c * 8;
            else                src = Wl_g + (size_t)(n0 + r) * CK + k0 + c * 8;
            cpa16(dbase + (uint32_t)(tile * TSZ + r * GP + c * 8) * 2, src);
        }
        asm volatile("cp.async.commit_group;");
    };

    float acc[4][4][4];
#pragma unroll
    for (int a = 0; a < 4; a++)
#pragma unroll
        for (int b = 0; b < 4; b++)
#pragma unroll
            for (int c = 0; c < 4; c++) acc[a][b][c] = 0.f;

    issue(0, 0);
    for (int blk = 0; blk < 8; blk++) {
        const int buf = blk & 1;
        if (blk < 7) issue(buf ^ 1, (blk + 1) * 64);
        if (blk < 7) asm volatile("cp.async.wait_group 1;");
        else         asm volatile("cp.async.wait_group 0;");
        __syncthreads();

        const __nv_bfloat16* Ah = fs + buf * PJ_STAGE;
        const __nv_bfloat16* Al = Ah + TSZ;
        const __nv_bfloat16* Wh = Ah + 2 * TSZ;
        const __nv_bfloat16* Wl = Ah + 3 * TSZ;

#pragma unroll
        for (int ks = 0; ks < 4; ks++) {
            uint32_t ah[4][4], al[4][4];
#pragma unroll
            for (int mt = 0; mt < 4; mt++) {
                const __nv_bfloat16* ar = Ah + (wm * 64 + mt * 16 + lq) * GP + ks * 16 + lk;
                ah[mt][0] = *(const uint32_t*)ar;
                ah[mt][1] = *(const uint32_t*)(ar + 8 * GP);
                ah[mt][2] = *(const uint32_t*)(ar + 8);
                ah[mt][3] = *(const uint32_t*)(ar + 8 * GP + 8);
                const __nv_bfloat16* al_ = Al + (wm * 64 + mt * 16 + lq) * GP + ks * 16 + lk;
                al[mt][0] = *(const uint32_t*)al_;
                al[mt][1] = *(const uint32_t*)(al_ + 8 * GP);
                al[mt][2] = *(const uint32_t*)(al_ + 8);
                al[mt][3] = *(const uint32_t*)(al_ + 8 * GP + 8);
            }
#pragma unroll
            for (int nt = 0; nt < 4; nt++) {
                const __nv_bfloat16* bh = Wh + (wn * 32 + nt * 8 + lq) * GP + ks * 16 + lk;
                uint32_t bh0 = *(const uint32_t*)bh;
                uint32_t bh1 = *(const uint32_t*)(bh + 8);
                const __nv_bfloat16* bl = Wl + (wn * 32 + nt * 8 + lq) * GP + ks * 16 + lk;
                uint32_t bl0 = *(const uint32_t*)bl;
                uint32_t bl1 = *(const uint32_t*)(bl + 8);
#pragma unroll
                for (int mt = 0; mt < 4; mt++) {
                    mma16816(acc[mt][nt], ah[mt][0], ah[mt][1], ah[mt][2], ah[mt][3], bh0, bh1);
                    mma16816(acc[mt][nt], ah[mt][0], ah[mt][1], ah[mt][2], ah[mt][3], bl0, bl1);
                    mma16816(acc[mt][nt], al[mt][0], al[mt][1], al[mt][2], al[mt][3], bh0, bh1);
                }
            }
        }
        __syncthreads();
    }

#pragma unroll
    for (int mt = 0; mt < 4; mt++) {
#pragma unroll
        for (int nt = 0; nt < 4; nt++) {
            int row = m0 + wm * 64 + mt * 16 + lq;
            int col = n0 + wn * 32 + nt * 8 + lk;
            float b0 = bias[col], b1 = bias[col + 1];
#pragma unroll
            for (int half = 0; half < 2; half++) {
                int r = row + half * 8;
                float2 v;
                v.x = acc[mt][nt][half * 2 + 0] + b0;
                v.y = acc[mt][nt][half * 2 + 1] + b1;
                *(float2*)(C + (size_t)r * CE + col) = v;
            }
        }
    }
}

// ---------------- per-row norms (merged q + k) ----------------
__global__ void __launch_bounds__(256) norm_all_kernel()
{
    int blk = blockIdx.x;
    int row = (blk & 8191) * 8 + (threadIdx.x >> 5);
    int lane = threadIdx.x & 31;
    if (blk < 8192) {
        const float* p = g_qh + (size_t)row * 64;
        float a = p[lane], b = p[lane + 32];
        float s = a * a + b * b;
#pragma unroll
        for (int o = 16; o; o >>= 1) s += __shfl_down_sync(0xffffffffu, s, o);
        if (lane == 0) g_ll[row] = s;
    } else {
        const float* p1 = g_k1h + (size_t)row * 64;
        const float* p2 = g_k2h + (size_t)row * 64;
        float x0 = p1[lane], x1 = p1[lane + 32];
        float y0 = p2[lane], y1 = p2[lane + 32];
        float svv = x0 * x0 + x1 * x1;
        float saa = y0 * y0 + y1 * y1;
        float sva = x0 * y0 + x1 * y1;
#pragma unroll
        for (int o = 16; o; o >>= 1) {
            svv += __shfl_down_sync(0xffffffffu, svv, o);
            saa += __shfl_down_sync(0xffffffffu, saa, o);
            sva += __shfl_down_sync(0xffffffffu, sva, o);
        }
        if (lane == 0) { g_vv[row] = svv; g_aa[row] = saa; g_va[row] = sva; }
    }
}

// ---------------- V sum + transpose -> bf16 hi/lo VT [bh][d][s] ----------------
__global__ void __launch_bounds__(256) prep_vt()
{
    __shared__ float tile[64 * 65];
    const int bh = blockIdx.y;
    const int s0 = blockIdx.x * 64;
    const int tid = threadIdx.x;
    const float* vp = g_vh + (size_t)(bh * 1024 + s0) * 64;
    const float* vp2 = g_v2 + (size_t)(bh * 1024 + s0) * 64;
#pragma unroll
    for (int u = 0; u < 4; u++) {
        int id = tid + u * 256;
        int r = id >> 4, c4 = (id & 15) * 4;
        float4 x = *(const float4*)(vp + r * 64 + c4);
        float4 y = *(const float4*)(vp2 + r * 64 + c4);
        tile[r * 65 + c4 + 0] = x.x + y.x;
        tile[r * 65 + c4 + 1] = x.y + y.y;
        tile[r * 65 + c4 + 2] = x.z + y.z;
        tile[r * 65 + c4 + 3] = x.w + y.w;
    }
    __syncthreads();
#pragma unroll
    for (int u = 0; u < 8; u++) {
        int id = tid + u * 256;
        int d = id >> 5, sp = id & 31;
        float x0 = tile[(2 * sp) * 65 + d];
        float x1 = tile[(2 * sp + 1) * 65 + d];
        size_t off = ((size_t)(bh * 64 + d) * 1024 + s0 + 2 * sp);
        *(uint32_t*)(g_vthb + off) = pk_hi(x0, x1);
        *(uint32_t*)(g_vtlb + off) = pk_lo(x0, x1);
    }
}

// =====================================================================
// flash_mma: 64 q-rows/CTA (grid 16x64, tail waste 1.2%), 256 threads,
//   8 warps = 4 row-groups x 2 s-halves; double-buffered staging.
// =====================================================================
#define FK (64 * GP)
#define FL_SMEM_B (2 * 6 * FK * 2)

__global__ void __launch_bounds__(256) flash_mma()
{
    extern __shared__ __nv_bfloat16 fs[];
    const uint32_t sbs = smem_u32(fs);

    const int tid = threadIdx.x;
    const int wid = tid >> 5, lane = tid & 31;
    const int wp = wid >> 1;            // row group 0..3 (16 rows each)
    const int wh = wid & 1;             // s-half 0/1
    const int lq = lane >> 2;
    const int lk = (lane & 3) * 2;
    const int bh = blockIdx.y;
    const int l0 = blockIdx.x * 64;
    const int bhS = bh * 1024;

    uint32_t qh[4][4], ql[4][4];
    {
        const float* q0 = g_qh + (size_t)(bhS + l0 + wp * 16 + lq) * 64;
        const float* q8 = q0 + 8 * 64;
#pragma unroll
        for (int ks = 0; ks < 4; ks++) {
            float2 x00 = *(const float2*)(q0 + ks * 16 + lk);
            float2 x10 = *(const float2*)(q8 + ks * 16 + lk);
            float2 x01 = *(const float2*)(q0 + ks * 16 + lk + 8);
            float2 x11 = *(const float2*)(q8 + ks * 16 + lk + 8);
            qh[ks][0] = pk_hi(x00.x, x00.y); ql[ks][0] = pk_lo(x00.x, x00.y);
            qh[ks][1] = pk_hi(x10.x, x10.y); ql[ks][1] = pk_lo(x10.x, x10.y);
            qh[ks][2] = pk_hi(x01.x, x01.y); ql[ks][2] = pk_lo(x01.x, x01.y);
            qh[ks][3] = pk_hi(x11.x, x11.y); ql[ks][3] = pk_lo(x11.x, x11.y);
        }
    }
    const float ll0 = g_ll[bhS + l0 + wp * 16 + lq];
    const float ll1 = g_ll[bhS + l0 + wp * 16 + lq + 8];

    float ls0 = 0.f, ls1 = 0.f;
    float o[8][4];
#pragma unroll
    for (int dt = 0; dt < 8; dt++)
#pragma unroll
        for (int c = 0; c < 4; c++) o[dt][c] = 0.f;

    auto issue = [&](int buf, int s0) {
        const uint32_t dbase = sbs + (uint32_t)buf * (6 * FK * 2);
#pragma unroll
        for (int t = 0; t < 12; t++) {
            int cid = tid + t * 256;
            int tile = cid >> 9;
            int r = (cid >> 3) & 63;
            int c = cid & 7;
            const __nv_bfloat16* src;
            if (tile == 0)      src = g_k1hb + ((size_t)(bhS + s0 + r) * 64 + c * 8);
            else if (tile == 1) src = g_k1lb + ((size_t)(bhS + s0 + r) * 64 + c * 8);
            else if (tile == 2) src = g_k2hb + ((size_t)(bhS + s0 + r) * 64 + c * 8);
            else if (tile == 3) src = g_k2lb + ((size_t)(bhS + s0 + r) * 64 + c * 8);
            else if (tile == 4) src = g_vthb + ((size_t)(bh * 64 + r) * 1024 + s0 + c * 8);
            else                src = g_vtlb + ((size_t)(bh * 64 + r) * 1024 + s0 + c * 8);
            cpa16(dbase + (uint32_t)(tile * FK + r * GP + c * 8) * 2, src);
        }
        asm volatile("cp.async.commit_group;");
    };

    issue(0, 0);

    for (int it = 0; it < 16; it++) {
        const int buf = it & 1;
        const int s0 = it * 64;
        if (it < 15) issue(buf ^ 1, s0 + 64);
        if (it < 15) asm volatile("cp.async.wait_group 1;");
        else         asm volatile("cp.async.wait_group 0;");
        __syncthreads();

        const __nv_bfloat16* Kb  = fs + buf * (6 * FK);
        const __nv_bfloat16* K1h = Kb;
        const __nv_bfloat16* K1l = Kb + FK;
        const __nv_bfloat16* K2h = Kb + 2 * FK;
        const __nv_bfloat16* K2l = Kb + 3 * FK;
        const __nv_bfloat16* VTh = Kb + 4 * FK;
        const __nv_bfloat16* VTl = Kb + 5 * FK;

        float lv[4][4], la[4][4];
#pragma unroll
        for (int nt = 0; nt < 4; nt++)
#pragma unroll
            for (int c = 0; c < 4; c++) { lv[nt][c] = 0.f; la[nt][c] = 0.f; }

        // QK: this warp covers s = wh*32 + nt*8 .. (+7); ks outer for ILP
#pragma unroll
        for (int ks = 0; ks < 4; ks++) {
#pragma unroll
            for (int nt = 0; nt < 4; nt++) {
                const __nv_bfloat16* b1h = K1h + (wh * 32 + nt * 8 + lq) * GP + ks * 16 + lk;
                uint32_t h0 = *(const uint32_t*)b1h;
                uint32_t h1 = *(const uint32_t*)(b1h + 8);
                const __nv_bfloat16* b1l = K1l + (wh * 32 + nt * 8 + lq) * GP + ks * 16 + lk;
                uint32_t l0_ = *(const uint32_t*)b1l;
                uint32_t l1_ = *(const uint32_t*)(b1l + 8);
                mma16816(lv[nt], qh[ks][0], qh[ks][1], qh[ks][2], qh[ks][3], h0, h1);
                mma16816(lv[nt], qh[ks][0], qh[ks][1], qh[ks][2], qh[ks][3], l0_, l1_);
                mma16816(lv[nt], ql[ks][0], ql[ks][1], ql[ks][2], ql[ks][3], h0, h1);
                const __nv_bfloat16* b2h = K2h + (wh * 32 + nt * 8 + lq) * GP + ks * 16 + lk;
                uint32_t g0 = *(const uint32_t*)b2h;
                uint32_t g1 = *(const uint32_t*)(b2h + 8);
                const __nv_bfloat16* b2l = K2l + (wh * 32 + nt * 8 + lq) * GP + ks * 16 + lk;
                uint32_t e0 = *(const uint32_t*)b2l;
                uint32_t e1 = *(const uint32_t*)(b2l + 8);
                mma16816(la[nt], qh[ks][0], qh[ks][1], qh[ks][2], qh[ks][3], g0, g1);
                mma16816(la[nt], qh[ks][0], qh[ks][1], qh[ks][2], qh[ks][3], e0, e1);
                mma16816(la[nt], ql[ks][0], ql[ks][1], ql[ks][2], ql[ks][3], g0, g1);
            }
        }

        // gram-det -> p = exp(-sqrt(det)) (fixed max 0)
#pragma unroll
        for (int nt = 0; nt < 4; nt++) {
            int sidx = bhS + s0 + wh * 32 + nt * 8 + lk;
            float2 vv2 = *(const float2*)(g_vv + sidx);
            float2 aa2 = *(const float2*)(g_aa + sidx);
            float2 va2 = *(const float2*)(g_va + sidx);
            float g2x = vv2.x * aa2.x - va2.x * va2.x;
            float g2y = vv2.y * aa2.y - va2.y * va2.y;
            {
                float LV = lv[nt][0], LA = la[nt][0];
                float det = ll0 * g2x - LV * (LV * aa2.x - LA * va2.x) + LA * (LV * va2.x - LA * vv2.x);
                float p = pexp_negsqrt(det);
                lv[nt][0] = p; ls0 += p;
            }
            {
                float LV = lv[nt][1], LA = la[nt][1];
                float det = ll0 * g2y - LV * (LV * aa2.y - LA * va2.y) + LA * (LV * va2.y - LA * vv2.y);
                float p = pexp_negsqrt(det);
                lv[nt][1] = p; ls0 += p;
            }
            {
                float LV = lv[nt][2], LA = la[nt][2];
                float det = ll1 * g2x - LV * (LV * aa2.x - LA * va2.x) + LA * (LV * va2.x - LA * vv2.x);
                float p = pexp_negsqrt(det);
                lv[nt][2] = p; ls1 += p;
            }
            {
                float LV = lv[nt][3], LA = la[nt][3];
                float det = ll1 * g2y - LV * (LV * aa2.y - LA * va2.y) + LA * (LV * va2.y - LA * vv2.y);
                float p = pexp_negsqrt(det);
                lv[nt][3] = p; ls1 += p;
            }
        }

        uint32_t ph[2][4], pl[2][4];
#pragma unroll
        for (int ksl = 0; ksl < 2; ksl++) {
            ph[ksl][0] = pk_hi(lv[2 * ksl][0], lv[2 * ksl][1]);
            pl[ksl][0] = pk_lo(lv[2 * ksl][0], lv[2 * ksl][1]);
            ph[ksl][1] = pk_hi(lv[2 * ksl][2], lv[2 * ksl][3]);
            pl[ksl][1] = pk_lo(lv[2 * ksl][2], lv[2 * ksl][3]);
            ph[ksl][2] = pk_hi(lv[2 * ksl + 1][0], lv[2 * ksl + 1][1]);
            pl[ksl][2] = pk_lo(lv[2 * ksl + 1][0], lv[2 * ksl + 1][1]);
            ph[ksl][3] = pk_hi(lv[2 * ksl + 1][2], lv[2 * ksl + 1][3]);
            pl[ksl][3] = pk_lo(lv[2 * ksl + 1][2], lv[2 * ksl + 1][3]);
        }

        // PV: this warp's s-half = k-steps wh*2 + {0,1}
#pragma unroll
        for (int ksl = 0; ksl < 2; ksl++) {
#pragma unroll
            for (int dt = 0; dt < 8; dt++) {
                const __nv_bfloat16* vh = VTh + (dt * 8 + lq) * GP + wh * 32 + ksl * 16 + lk;
                uint32_t vh0 = *(const uint32_t*)vh;
                uint32_t vh1 = *(const uint32_t*)(vh + 8);
                const __nv_bfloat16* vl = VTl + (dt * 8 + lq) * GP + wh * 32 + ksl * 16 + lk;
                uint32_t vl0 = *(const uint32_t*)vl;
                uint32_t vl1 = *(const uint32_t*)(vl + 8);
                mma16816(o[dt], ph[ksl][0], ph[ksl][1], ph[ksl][2], ph[ksl][3], vh0, vh1);
                mma16816(o[dt], ph[ksl][0], ph[ksl][1], ph[ksl][2], ph[ksl][3], vl0, vl1);
                mma16816(o[dt], pl[ksl][0], pl[ksl][1], pl[ksl][2], pl[ksl][3], vh0, vh1);
            }
        }
        __syncthreads();
    }

    // quad-level row-sum reduce
    ls0 += __shfl_xor_sync(0xffffffffu, ls0, 1);
    ls0 += __shfl_xor_sync(0xffffffffu, ls0, 2);
    ls1 += __shfl_xor_sync(0xffffffffu, ls1, 1);
    ls1 += __shfl_xor_sync(0xffffffffu, ls1, 2);

    // cross s-half reduce via smem (staging buffer is free now)
    float* red = (float*)fs;
    const int rbase = (wp * 32 + lane) * 34;
    if (wh == 1) {
#pragma unroll
        for (int dt = 0; dt < 8; dt++) {
#pragma unroll
            for (int c = 0; c < 4; c++) red[rbase + dt * 4 + c] = o[dt][c];
        }
        red[rbase + 32] = ls0;
        red[rbase + 33] = ls1;
    }
    __syncthreads();
    if (wh == 0) {
#pragma unroll
        for (int dt = 0; dt < 8; dt++)
#pragma unroll
            for (int c = 0; c < 4; c++) o[dt][c] += red[rbase + dt * 4 + c];
        ls0 += red[rbase + 32];
        ls1 += red[rbase + 33];

        const float inv0 = frcp_pos(ls0);
        const float inv1 = frcp_pos(ls1);
        const int bi = bh >> 3, h = bh & 7;
        const int r0 = l0 + wp * 16 + lq;
#pragma unroll
        for (int dt = 0; dt < 8; dt++) {
            int d = dt * 8 + lk;
            float a0 = o[dt][0] * inv0, a1 = o[dt][1] * inv0;
            float b0 = o[dt][2] * inv1, b1 = o[dt][3] * inv1;
            size_t off0 = (size_t)(r0 * 8 + bi) * 512 + h * 64 + d;
            size_t off1 = (size_t)((r0 + 8) * 8 + bi) * 512 + h * 64 + d;
            *(uint32_t*)(g_aoh + off0) = pk_hi(a0, a1);
            *(uint32_t*)(g_aol + off0) = pk_lo(a0, a1);
            *(uint32_t*)(g_aoh + off1) = pk_hi(b0, b1);
            *(uint32_t*)(g_aol + off1) = pk_lo(b0, b1);
        }
    }
}

// ---------------- launch ----------------
extern "C" void kernel_launch(void* const* d_in, const int* in_sizes, int n_in,
                              void* d_out, int out_size) {
    const float* query = (const float*)d_in[0];
    const float* mod1  = (const float*)d_in[1];
    const float* mod2  = (const float*)d_in[2];
    const float* Wq  = (const float*)d_in[3];  const float* bq  = (const float*)d_in[4];
    const float* Wk1 = (const float*)d_in[5];  const float* bk1 = (const float*)d_in[6];
    const float* Wk2 = (const float*)d_in[7];  const float* bk2 = (const float*)d_in[8];
    const float* Wv1 = (const float*)d_in[9];  const float* bv1 = (const float*)d_in[10];
    const float* Wv2 = (const float*)d_in[11]; const float* bv2 = (const float*)d_in[12];
    const float* Wg1 = (const float*)d_in[13]; const float* bg1 = (const float*)d_in[14];
    const float* Wg2 = (const float*)d_in[15]; const float* bg2 = (const float*)d_in[16];
    const float* Wo  = (const float*)d_in[17]; const float* bo  = (const float*)d_in[18];
    float* out = (float*)d_out;

    cudaFuncSetAttribute(proj3_cp,    cudaFuncAttributeMaxDynamicSharedMemorySize, PJ_SMEM_B);
    cudaFuncSetAttribute(proj_out_cp, cudaFuncAttributeMaxDynamicSharedMemorySize, PJ_SMEM_B);
    cudaFuncSetAttribute(projvg_cp,   cudaFuncAttributeMaxDynamicSharedMemorySize, VG_SMEM_B);
    cudaFuncSetAttribute(flash_mma,   cudaFuncAttributeMaxDynamicSharedMemorySize, FL_SMEM_B);

    dim3 pb(256);
    prep_act<<<dim3(4096, 1, 3), pb>>>(query, mod1, mod2);
    prep_w<<<dim3(256, 1, 8), pb>>>(Wq, Wk1, Wk2, Wv1, Wv2, Wg1, Wg2, Wo);
    proj3_cp<<<dim3(64, 4, 3), pb, PJ_SMEM_B>>>(bq, bk1, bk2);
    projvg_cp<<<dim3(64, 4, 2), pb, VG_SMEM_B>>>(bv1, bg1, bv2, bg2);
    norm_all_kernel<<<16384, 256>>>();
    prep_vt<<<dim3(16, 64), 256>>>();
    flash_mma<<<dim3(16, 64), 256, FL_SMEM_B>>>();
    proj_out_cp<<<dim3(64, 4), pb, PJ_SMEM_B>>>(bo, out);
}

// round 16
// speedup vs baseline: 1.0201x; 1.0201x over previous
#include <cuda_runtime.h>
#include <cuda_bf16.h>
#include <cstdint>

#define CL   1024
#define CS   1024
#define CB   8
#define CE   512
#define CH   8
#define CDH  64
#define CBH  64
#define CM   8192
#define CK   512
#define WSZ  (CE * CK)

// ---------------- device scratch ----------------
__device__ __align__(128) float g_qh [CBH * CL * CDH];
__device__ __align__(128) float g_k1h[CBH * CS * CDH];
__device__ __align__(128) float g_k2h[CBH * CS * CDH];
__device__ __align__(128) float g_vh [CBH * CS * CDH];
__device__ __align__(128) float g_v2 [CBH * CS * CDH];
__device__ __align__(128) float g_ll [CBH * CL];
__device__ __align__(128) float g_vv [CBH * CS];
__device__ __align__(128) float g_aa [CBH * CS];
__device__ __align__(128) float g_va [CBH * CS];
// bf16 hi/lo operand caches
__device__ __align__(128) __nv_bfloat16 g_k1hb[CBH * CS * CDH];
__device__ __align__(128) __nv_bfloat16 g_k1lb[CBH * CS * CDH];
__device__ __align__(128) __nv_bfloat16 g_k2hb[CBH * CS * CDH];
__device__ __align__(128) __nv_bfloat16 g_k2lb[CBH * CS * CDH];
__device__ __align__(128) __nv_bfloat16 g_vthb[CBH * CDH * CS];   // [bh][d][s]
__device__ __align__(128) __nv_bfloat16 g_vtlb[CBH * CDH * CS];
// pre-split GEMM operands
__device__ __align__(128) __nv_bfloat16 g_qryh[CM * CK];
__device__ __align__(128) __nv_bfloat16 g_qryl[CM * CK];
__device__ __align__(128) __nv_bfloat16 g_m1h [CM * CK];
__device__ __align__(128) __nv_bfloat16 g_m1l [CM * CK];
__device__ __align__(128) __nv_bfloat16 g_m2h [CM * CK];
__device__ __align__(128) __nv_bfloat16 g_m2l [CM * CK];
__device__ __align__(128) __nv_bfloat16 g_wh  [8 * WSZ];
__device__ __align__(128) __nv_bfloat16 g_wl  [8 * WSZ];
__device__ __align__(128) __nv_bfloat16 g_aoh [CM * CE];
__device__ __align__(128) __nv_bfloat16 g_aol [CM * CE];

// ---------------- MUFU-free math ----------------
__device__ __forceinline__ float fexp(float x) {
    float t = x * 1.4426950408889634f;
    t = fminf(fmaxf(t, -126.0f), 126.0f);
    int i = __float2int_rn(t);
    float u = (t - (float)i) * 0.6931471805599453f;
    float p = 1.3888889e-3f;
    p = fmaf(p, u, 8.3333333e-3f);
    p = fmaf(p, u, 4.1666667e-2f);
    p = fmaf(p, u, 1.6666667e-1f);
    p = fmaf(p, u, 0.5f);
    p = fmaf(p, u, 1.0f);
    p = fmaf(p, u, 1.0f);
    return p * __int_as_float((i + 127) << 23);
}
__device__ __forceinline__ float frcp_pos(float x) {
    float y = __int_as_float(0x7EF127EAu - __float_as_int(x));
    y = y * (2.0f - x * y);
    y = y * (2.0f - x * y);
    y = y * (2.0f - x * y);
    return y;
}
// p = exp(-sqrt(max(det,1e-8))) — fused, MUFU-free, scores are always <= 0
__device__ __forceinline__ float pexp_negsqrt(float det) {
    det = fmaxf(det, 1e-8f);
    float y = __int_as_float(0x5f3759df - (__float_as_int(det) >> 1));
    y = y * fmaf(-0.5f * det, y * y, 1.5f);
    y = y * fmaf(-0.5f * det, y * y, 1.5f);
    float s = det * y;                                  // sqrt(det)
    float t = fmaxf(s * -1.4426950408889634f, -126.0f); // always <= 0
    int i = __float2int_rn(t);
    float u = (t - (float)i) * 0.6931471805599453f;
    float p = 8.3333333e-3f;
    p = fmaf(p, u, 4.1666667e-2f);
    p = fmaf(p, u, 1.6666667e-1f);
    p = fmaf(p, u, 0.5f);
    p = fmaf(p, u, 1.0f);
    p = fmaf(p, u, 1.0f);
    return p * __int_as_float((i + 127) << 23);
}

// ---------------- mma.sync bf16 helper ----------------
__device__ __forceinline__ void mma16816(float* c,
    uint32_t a0, uint32_t a1, uint32_t a2, uint32_t a3,
    uint32_t b0, uint32_t b1)
{
    asm volatile(
        "mma.sync.aligned.m16n8k16.row.col.f32.bf16.bf16.f32 "
        "{%0,%1,%2,%3},{%4,%5,%6,%7},{%8,%9},{%0,%1,%2,%3};"
        : "+f"(c[0]), "+f"(c[1]), "+f"(c[2]), "+f"(c[3])
        : "r"(a0), "r"(a1), "r"(a2), "r"(a3), "r"(b0), "r"(b1));
}

#define GP 72
#define TSZ (128 * GP)
__device__ __forceinline__ uint32_t pkbf(__nv_bfloat16 a, __nv_bfloat16 b) {
    __nv_bfloat162 t(a, b);
    return *reinterpret_cast<uint32_t*>(&t);
}
__device__ __forceinline__ uint32_t pk_hi(float x, float y) {
    return pkbf(__float2bfloat16(x), __float2bfloat16(y));
}
__device__ __forceinline__ uint32_t pk_lo(float x, float y) {
    __nv_bfloat16 hx = __float2bfloat16(x), hy = __float2bfloat16(y);
    return pkbf(__float2bfloat16(x - __bfloat162float(hx)),
                __float2bfloat16(y - __bfloat162float(hy)));
}
__device__ __forceinline__ uint32_t smem_u32(const void* p) {
    uint32_t a;
    asm("{ .reg .u64 t; cvta.to.shared.u64 t, %1; cvt.u32.u64 %0, t; }" : "=r"(a) : "l"(p));
    return a;
}
__device__ __forceinline__ void cpa16(uint32_t dst, const void* src) {
    asm volatile("cp.async.cg.shared.global [%0], [%1], 16;" :: "r"(dst), "l"(src));
}

// ---------------- prep_all: activations (3x) + weights (8x) in one launch ----------------
__global__ void __launch_bounds__(256)
prep_all(const float* __restrict__ q, const float* __restrict__ m1,
         const float* __restrict__ m2,
         const float* __restrict__ w0, const float* __restrict__ w1,
         const float* __restrict__ w2, const float* __restrict__ w3,
         const float* __restrict__ w4, const float* __restrict__ w5,
         const float* __restrict__ w6, const float* __restrict__ w7)
{
    const int b = blockIdx.x;
    if (b < 12288) {
        const int z = b >> 12;          // 4096 blocks per activation
        const int bx = b & 4095;
        const float* src = (z == 0) ? q : (z == 1) ? m1 : m2;
        __nv_bfloat16* H = (z == 0) ? g_qryh : (z == 1) ? g_m1h : g_m2h;
        __nv_bfloat16* L = (z == 0) ? g_qryl : (z == 1) ? g_m1l : g_m2l;
        size_t i4 = (size_t)bx * 256 + threadIdx.x;
        float4 x = ((const float4*)src)[i4];
        ((uint2*)H)[i4] = make_uint2(pk_hi(x.x, x.y), pk_hi(x.z, x.w));
        ((uint2*)L)[i4] = make_uint2(pk_lo(x.x, x.y), pk_lo(x.z, x.w));
    } else {
        const int zz = (b - 12288) >> 8;  // 256 blocks per weight
        const int bx = (b - 12288) & 255;
        const float* src;
        switch (zz) {
            case 0: src = w0; break; case 1: src = w1; break;
            case 2: src = w2; break; case 3: src = w3; break;
            case 4: src = w4; break; case 5: src = w5; break;
            case 6: src = w6; break; default: src = w7; break;
        }
        size_t i4 = (size_t)bx * 256 + threadIdx.x;
        float4 x = ((const float4*)src)[i4];
        ((uint2*)(g_wh + (size_t)zz * WSZ))[i4] = make_uint2(pk_hi(x.x, x.y), pk_hi(x.z, x.w));
        ((uint2*)(g_wl + (size_t)zz * WSZ))[i4] = make_uint2(pk_lo(x.x, x.y), pk_lo(x.z, x.w));
    }
}

// =====================================================================
// proj3_cp: q/k1/k2 projections (unchanged, best config)
// =====================================================================
#define PJ_STAGE (4 * TSZ)
#define PJ_SMEM_B (2 * PJ_STAGE * 2)

__global__ void __launch_bounds__(256)
proj3_cp(const float* __restrict__ bq, const float* __restrict__ bk1,
         const float* __restrict__ bk2)
{
    extern __shared__ __nv_bfloat16 fs[];
    const uint32_t sbs = smem_u32(fs);
    const int z = blockIdx.z;
    const __nv_bfloat16* Ah_g = (z == 0) ? g_qryh : (z == 1) ? g_m1h : g_m2h;
    const __nv_bfloat16* Al_g = (z == 0) ? g_qryl : (z == 1) ? g_m1l : g_m2l;
    const __nv_bfloat16* Wh_g = g_wh + (size_t)z * WSZ;
    const __nv_bfloat16* Wl_g = g_wl + (size_t)z * WSZ;
    const float* bias = (z == 0) ? bq : (z == 1) ? bk1 : bk2;
    float* C = (z == 0) ? g_qh : (z == 1) ? g_k1h : g_k2h;
    __nv_bfloat16* CHo = (z == 1) ? g_k1hb : g_k2hb;
    __nv_bfloat16* CLo = (z == 1) ? g_k1lb : g_k2lb;

    const int tid = threadIdx.x;
    const int wid = tid >> 5, lane = tid & 31;
    const int wm = wid >> 2, wn = wid & 3;
    const int m0 = blockIdx.x * 128;
    const int n0 = blockIdx.y * 128;
    const int lq = lane >> 2;
    const int lk = (lane & 3) * 2;

    auto issue = [&](int buf, int k0) {
        const uint32_t dbase = sbs + (uint32_t)buf * (PJ_STAGE * 2);
#pragma unroll
        for (int t = 0; t < 16; t++) {
            int cid = tid + t * 256;
            int tile = cid >> 10;
            int r = (cid >> 3) & 127;
            int c = cid & 7;
            const __nv_bfloat16* src;
            if (tile == 0)      src = Ah_g + (size_t)(m0 + r) * CK + k0 + c * 8;
            else if (tile == 1) src = Al_g + (size_t)(m0 + r) * CK + k0 + c * 8;
            else if (tile == 2) src = Wh_g + (size_t)(n0 + r) * CK + k0 + c * 8;
            else                src = Wl_g + (size_t)(n0 + r) * CK + k0 + c * 8;
            cpa16(dbase + (uint32_t)(tile * TSZ + r * GP + c * 8) * 2, src);
        }
        asm volatile("cp.async.commit_group;");
    };

    float acc[4][4][4];
#pragma unroll
    for (int a = 0; a < 4; a++)
#pragma unroll
        for (int b = 0; b < 4; b++)
#pragma unroll
            for (int c = 0; c < 4; c++) acc[a][b][c] = 0.f;

    issue(0, 0);
    for (int blk = 0; blk < 8; blk++) {
        const int buf = blk & 1;
        if (blk < 7) issue(buf ^ 1, (blk + 1) * 64);
        if (blk < 7) asm volatile("cp.async.wait_group 1;");
        else         asm volatile("cp.async.wait_group 0;");
        __syncthreads();

        const __nv_bfloat16* Ah = fs + buf * PJ_STAGE;
        const __nv_bfloat16* Al = Ah + TSZ;
        const __nv_bfloat16* Wh = Ah + 2 * TSZ;
        const __nv_bfloat16* Wl = Ah + 3 * TSZ;

#pragma unroll
        for (int ks = 0; ks < 4; ks++) {
            uint32_t ah[4][4], al[4][4];
#pragma unroll
            for (int mt = 0; mt < 4; mt++) {
                const __nv_bfloat16* ar = Ah + (wm * 64 + mt * 16 + lq) * GP + ks * 16 + lk;
                ah[mt][0] = *(const uint32_t*)ar;
                ah[mt][1] = *(const uint32_t*)(ar + 8 * GP);
                ah[mt][2] = *(const uint32_t*)(ar + 8);
                ah[mt][3] = *(const uint32_t*)(ar + 8 * GP + 8);
                const __nv_bfloat16* al_ = Al + (wm * 64 + mt * 16 + lq) * GP + ks * 16 + lk;
                al[mt][0] = *(const uint32_t*)al_;
                al[mt][1] = *(const uint32_t*)(al_ + 8 * GP);
                al[mt][2] = *(const uint32_t*)(al_ + 8);
                al[mt][3] = *(const uint32_t*)(al_ + 8 * GP + 8);
            }
#pragma unroll
            for (int nt = 0; nt < 4; nt++) {
                const __nv_bfloat16* bh = Wh + (wn * 32 + nt * 8 + lq) * GP + ks * 16 + lk;
                uint32_t bh0 = *(const uint32_t*)bh;
                uint32_t bh1 = *(const uint32_t*)(bh + 8);
                const __nv_bfloat16* bl = Wl + (wn * 32 + nt * 8 + lq) * GP + ks * 16 + lk;
                uint32_t bl0 = *(const uint32_t*)bl;
                uint32_t bl1 = *(const uint32_t*)(bl + 8);
#pragma unroll
                for (int mt = 0; mt < 4; mt++) {
                    mma16816(acc[mt][nt], ah[mt][0], ah[mt][1], ah[mt][2], ah[mt][3], bh0, bh1);
                    mma16816(acc[mt][nt], ah[mt][0], ah[mt][1], ah[mt][2], ah[mt][3], bl0, bl1);
                    mma16816(acc[mt][nt], al[mt][0], al[mt][1], al[mt][2], al[mt][3], bh0, bh1);
                }
            }
        }
        __syncthreads();
    }

    const float scale = (z == 0) ? 0.125f : 1.0f;
#pragma unroll
    for (int mt = 0; mt < 4; mt++) {
#pragma unroll
        for (int nt = 0; nt < 4; nt++) {
            int row = m0 + wm * 64 + mt * 16 + lq;
            int col = n0 + wn * 32 + nt * 8 + lk;
            float b0 = bias[col], b1 = bias[col + 1];
            int h = col >> 6, d = col & 63;
#pragma unroll
            for (int half = 0; half < 2; half++) {
                int r = row + half * 8;
                int t = r >> 3, bi = r & 7;
                float2 v;
                v.x = (acc[mt][nt][half * 2 + 0] + b0) * scale;
                v.y = (acc[mt][nt][half * 2 + 1] + b1) * scale;
                size_t off = ((size_t)(bi * 8 + h) * 1024 + t) * 64 + d;
                *(float2*)(C + off) = v;
                if (z >= 1) {
                    *(uint32_t*)(CHo + off) = pk_hi(v.x, v.y);
                    *(uint32_t*)(CLo + off) = pk_lo(v.x, v.y);
                }
            }
        }
    }
}

// =====================================================================
// projvg_cp: gated value projection, grid.z = modality (unchanged)
// =====================================================================
#define VG_STAGE (6 * TSZ)
#define VG_SMEM_B (2 * VG_STAGE * 2)

__global__ void __launch_bounds__(256)
projvg_cp(const float* __restrict__ bv1, const float* __restrict__ bg1,
          const float* __restrict__ bv2, const float* __restrict__ bg2)
{
    extern __shared__ __nv_bfloat16 fs[];
    const uint32_t sbs = smem_u32(fs);
    const int mod = blockIdx.z;
    const __nv_bfloat16* Ah_g = mod ? g_m2h : g_m1h;
    const __nv_bfloat16* Al_g = mod ? g_m2l : g_m1l;
    const __nv_bfloat16* Vh_g = g_wh + (size_t)(3 + mod) * WSZ;
    const __nv_bfloat16* Vl_g = g_wl + (size_t)(3 + mod) * WSZ;
    const __nv_bfloat16* Gh_g = g_wh + (size_t)(5 + mod) * WSZ;
    const __nv_bfloat16* Gl_g = g_wl + (size_t)(5 + mod) * WSZ;
    const float* bv = mod ? bv2 : bv1;
    const float* bg = mod ? bg2 : bg1;
    float* Cdst = mod ? g_v2 : g_vh;

    const int tid = threadIdx.x;
    const int wid = tid >> 5, lane = tid & 31;
    const int wm = wid >> 2, wn = wid & 3;
    const int m0 = blockIdx.x * 128;
    const int n0 = blockIdx.y * 128;
    const int lq = lane >> 2;
    const int lk = (lane & 3) * 2;

    auto issue = [&](int buf, int k0) {
        const uint32_t dbase = sbs + (uint32_t)buf * (VG_STAGE * 2);
#pragma unroll
        for (int t = 0; t < 24; t++) {
            int cid = tid + t * 256;
            int tile = cid >> 10;
            int r = (cid >> 3) & 127;
            int c = cid & 7;
            const __nv_bfloat16* src;
            if (tile == 0)      src = Ah_g + (size_t)(m0 + r) * CK + k0 + c * 8;
            else if (tile == 1) src = Al_g + (size_t)(m0 + r) * CK + k0 + c * 8;
            else if (tile == 2) src = Vh_g + (size_t)(n0 + r) * CK + k0 + c * 8;
            else if (tile == 3) src = Vl_g + (size_t)(n0 + r) * CK + k0 + c * 8;
            else if (tile == 4) src = Gh_g + (size_t)(n0 + r) * CK + k0 + c * 8;
            else                src = Gl_g + (size_t)(n0 + r) * CK + k0 + c * 8;
            cpa16(dbase + (uint32_t)(tile * TSZ + r * GP + c * 8) * 2, src);
        }
        asm volatile("cp.async.commit_group;");
    };

    float av_[4][4][4], ag_[4][4][4];
#pragma unroll
    for (int a = 0; a < 4; a++)
#pragma unroll
        for (int b = 0; b < 4; b++)
#pragma unroll
            for (int c = 0; c < 4; c++) { av_[a][b][c] = 0.f; ag_[a][b][c] = 0.f; }

    issue(0, 0);
    for (int blk = 0; blk < 8; blk++) {
        const int buf = blk & 1;
        if (blk < 7) issue(buf ^ 1, (blk + 1) * 64);
        if (blk < 7) asm volatile("cp.async.wait_group 1;");
        else         asm volatile("cp.async.wait_group 0;");
        __syncthreads();

        const __nv_bfloat16* Ah = fs + buf * VG_STAGE;
        const __nv_bfloat16* Al = Ah + TSZ;
        const __nv_bfloat16* Vh = Ah + 2 * TSZ;
        const __nv_bfloat16* Vl = Ah + 3 * TSZ;
        const __nv_bfloat16* Gh = Ah + 4 * TSZ;
        const __nv_bfloat16* Gl = Ah + 5 * TSZ;

#pragma unroll
        for (int ks = 0; ks < 4; ks++) {
            uint32_t ah[4][4], al[4][4];
#pragma unroll
            for (int mt = 0; mt < 4; mt++) {
                const __nv_bfloat16* ar = Ah + (wm * 64 + mt * 16 + lq) * GP + ks * 16 + lk;
                ah[mt][0] = *(const uint32_t*)ar;
                ah[mt][1] = *(const uint32_t*)(ar + 8 * GP);
                ah[mt][2] = *(const uint32_t*)(ar + 8);
                ah[mt][3] = *(const uint32_t*)(ar + 8 * GP + 8);
                const __nv_bfloat16* al_ = Al + (wm * 64 + mt * 16 + lq) * GP + ks * 16 + lk;
                al[mt][0] = *(const uint32_t*)al_;
                al[mt][1] = *(const uint32_t*)(al_ + 8 * GP);
                al[mt][2] = *(const uint32_t*)(al_ + 8);
                al[mt][3] = *(const uint32_t*)(al_ + 8 * GP + 8);
            }
#pragma unroll
            for (int nt = 0; nt < 4; nt++) {
                const __nv_bfloat16* vh = Vh + (wn * 32 + nt * 8 + lq) * GP + ks * 16 + lk;
                uint32_t vh0 = *(const uint32_t*)vh;
                uint32_t vh1 = *(const uint32_t*)(vh + 8);
                const __nv_bfloat16* vl = Vl + (wn * 32 + nt * 8 + lq) * GP + ks * 16 + lk;
                uint32_t vl0 = *(const uint32_t*)vl;
                uint32_t vl1 = *(const uint32_t*)(vl + 8);
                const __nv_bfloat16* gh = Gh + (wn * 32 + nt * 8 + lq) * GP + ks * 16 + lk;
                uint32_t gh0 = *(const uint32_t*)gh;
                uint32_t gh1 = *(const uint32_t*)(gh + 8);
                const __nv_bfloat16* gl = Gl + (wn * 32 + nt * 8 + lq) * GP + ks * 16 + lk;
                uint32_t gl0 = *(const uint32_t*)gl;
                uint32_t gl1 = *(const uint32_t*)(gl + 8);
#pragma unroll
                for (int mt = 0; mt < 4; mt++) {
                    mma16816(av_[mt][nt], ah[mt][0], ah[mt][1], ah[mt][2], ah[mt][3], vh0, vh1);
                    mma16816(av_[mt][nt], ah[mt][0], ah[mt][1], ah[mt][2], ah[mt][3], vl0, vl1);
                    mma16816(av_[mt][nt], al[mt][0], al[mt][1], al[mt][2], al[mt][3], vh0, vh1);
                    mma16816(ag_[mt][nt], ah[mt][0], ah[mt][1], ah[mt][2], ah[mt][3], gh0, gh1);
                    mma16816(ag_[mt][nt], ah[mt][0], ah[mt][1], ah[mt][2], ah[mt][3], gl0, gl1);
                    mma16816(ag_[mt][nt], al[mt][0], al[mt][1], al[mt][2], al[mt][3], gh0, gh1);
                }
            }
        }
        __syncthreads();
    }

#pragma unroll
    for (int mt = 0; mt < 4; mt++) {
#pragma unroll
        for (int nt = 0; nt < 4; nt++) {
            int row = m0 + wm * 64 + mt * 16 + lq;
            int col = n0 + wn * 32 + nt * 8 + lk;
            float bv0 = bv[col], bv1_ = bv[col + 1];
            float bg0 = bg[col], bg1_ = bg[col + 1];
            int h = col >> 6, d = col & 63;
#pragma unroll
            for (int half = 0; half < 2; half++) {
                int r = row + half * 8;
                int t = r >> 3, bi = r & 7;
                float vx0 = av_[mt][nt][half * 2 + 0] + bv0;
                float vx1 = av_[mt][nt][half * 2 + 1] + bv1_;
                float gx0 = ag_[mt][nt][half * 2 + 0] + bg0;
                float gx1 = ag_[mt][nt][half * 2 + 1] + bg1_;
                float2 v;
                v.x = vx0 * frcp_pos(1.0f + fexp(-gx0));
                v.y = vx1 * frcp_pos(1.0f + fexp(-gx1));
                *(float2*)(Cdst + ((size_t)(bi * 8 + h) * 1024 + t) * 64 + d) = v;
            }
        }
    }
}

// =====================================================================
// proj_out_cp: out = ao @ Wo^T + bo (unchanged)
// =====================================================================
__global__ void __launch_bounds__(256)
proj_out_cp(const float* __restrict__ bias, float* __restrict__ C)
{
    extern __shared__ __nv_bfloat16 fs[];
    const uint32_t sbs = smem_u32(fs);
    const __nv_bfloat16* Wh_g = g_wh + (size_t)7 * WSZ;
    const __nv_bfloat16* Wl_g = g_wl + (size_t)7 * WSZ;

    const int tid = threadIdx.x;
    const int wid = tid >> 5, lane = tid & 31;
    const int wm = wid >> 2, wn = wid & 3;
    const int m0 = blockIdx.x * 128;
    const int n0 = blockIdx.y * 128;
    const int lq = lane >> 2;
    const int lk = (lane & 3) * 2;

    auto issue = [&](int buf, int k0) {
        const uint32_t dbase = sbs + (uint32_t)buf * (PJ_STAGE * 2);
#pragma unroll
        for (int t = 0; t < 16; t++) {
            int cid = tid + t * 256;
            int tile = cid >> 10;
            int r = (cid >> 3) & 127;
            int c = cid & 7;
            const __nv_bfloat16* src;
            if (tile == 0)      src = g_aoh + (size_t)(m0 + r) * CE + k0 + c * 8;
            else if (tile == 1) src = g_aol + (size_t)(m0 + r) * CE + k0 + c * 8;
            else if (tile == 2) src = Wh_g + (size_t)(n0 + r) * CK + k0 + c * 8;
            else                src = Wl_g + (size_t)(n0 + r) * CK + k0 + c * 8;
            cpa16(dbase + (uint32_t)(tile * TSZ + r * GP + c * 8) * 2, src);
        }
        asm volatile("cp.async.commit_group;");
    };

    float acc[4][4][4];
#pragma unroll
    for (int a = 0; a < 4; a++)
#pragma unroll
        for (int b = 0; b < 4; b++)
#pragma unroll
            for (int c = 0; c < 4; c++) acc[a][b][c] = 0.f;

    issue(0, 0);
    for (int blk = 0; blk < 8; blk++) {
        const int buf = blk & 1;
        if (blk < 7) issue(buf ^ 1, (blk + 1) * 64);
        if (blk < 7) asm volatile("cp.async.wait_group 1;");
        else         asm volatile("cp.async.wait_group 0;");
        __syncthreads();

        const __nv_bfloat16* Ah = fs + buf * PJ_STAGE;
        const __nv_bfloat16* Al = Ah + TSZ;
        const __nv_bfloat16* Wh = Ah + 2 * TSZ;
        const __nv_bfloat16* Wl = Ah + 3 * TSZ;

#pragma unroll
        for (int ks = 0; ks < 4; ks++) {
            uint32_t ah[4][4], al[4][4];
#pragma unroll
            for (int mt = 0; mt < 4; mt++) {
                const __nv_bfloat16* ar = Ah + (wm * 64 + mt * 16 + lq) * GP + ks * 16 + lk;
                ah[mt][0] = *(const uint32_t*)ar;
                ah[mt][1] = *(const uint32_t*)(ar + 8 * GP);
                ah[mt][2] = *(const uint32_t*)(ar + 8);
                ah[mt][3] = *(const uint32_t*)(ar + 8 * GP + 8);
                const __nv_bfloat16* al_ = Al + (wm * 64 + mt * 16 + lq) * GP + ks * 16 + lk;
                al[mt][0] = *(const uint32_t*)al_;
                al[mt][1] = *(const uint32_t*)(al_ + 8 * GP);
                al[mt][2] = *(const uint32_t*)(al_ + 8);
                al[mt][3] = *(const uint32_t*)(al_ + 8 * GP + 8);
            }
#pragma unroll
            for (int nt = 0; nt < 4; nt++) {
                const __nv_bfloat16* bh = Wh + (wn * 32 + nt * 8 + lq) * GP + ks * 16 + lk;
                uint32_t bh0 = *(const uint32_t*)bh;
                uint32_t bh1 = *(const uint32_t*)(bh + 8);
                const __nv_bfloat16* bl = Wl + (wn * 32 + nt * 8 + lq) * GP + ks * 16 + lk;
                uint32_t bl0 = *(const uint32_t*)bl;
                uint32_t bl1 = *(const uint32_t*)(bl + 8);
#pragma unroll
                for (int mt = 0; mt < 4; mt++) {
                    mma16816(acc[mt][nt], ah[mt][0], ah[mt][1], ah[mt][2], ah[mt][3], bh0, bh1);
                    mma16816(acc[mt][nt], ah[mt][0], ah[mt][1], ah[mt][2], ah[mt][3], bl0, bl1);
                    mma16816(acc[mt][nt], al[mt][0], al[mt][1], al[mt][2], al[mt][3], bh0, bh1);
                }
            }
        }
        __syncthreads();
    }

#pragma unroll
    for (int mt = 0; mt < 4; mt++) {
#pragma unroll
        for (int nt = 0; nt < 4; nt++) {
            int row = m0 + wm * 64 + mt * 16 + lq;
            int col = n0 + wn * 32 + nt * 8 + lk;
            float b0 = bias[col], b1 = bias[col + 1];
#pragma unroll
            for (int half = 0; half < 2; half++) {
                int r = row + half * 8;
                float2 v;
                v.x = acc[mt][nt][half * 2 + 0] + b0;
                v.y = acc[mt][nt][half * 2 + 1] + b1;
                *(float2*)(C + (size_t)r * CE + col) = v;
            }
        }
    }
}

// ---------------- norm_prep: q/k norms + V sum/transpose in one launch ----------------
__global__ void __launch_bounds__(256) norm_prep()
{
    __shared__ float tile[64 * 65];
    const int blk = blockIdx.x;
    const int tid = threadIdx.x;
    if (blk < 8192) {
        int row = blk * 8 + (tid >> 5);
        int lane = tid & 31;
        const float* p = g_qh + (size_t)row * 64;
        float a = p[lane], b = p[lane + 32];
        float s = a * a + b * b;
#pragma unroll
        for (int o = 16; o; o >>= 1) s += __shfl_down_sync(0xffffffffu, s, o);
        if (lane == 0) g_ll[row] = s;
    } else if (blk < 16384) {
        int row = (blk - 8192) * 8 + (tid >> 5);
        int lane = tid & 31;
        const float* p1 = g_k1h + (size_t)row * 64;
        const float* p2 = g_k2h + (size_t)row * 64;
        float x0 = p1[lane], x1 = p1[lane + 32];
        float y0 = p2[lane], y1 = p2[lane + 32];
        float svv = x0 * x0 + x1 * x1;
        float saa = y0 * y0 + y1 * y1;
        float sva = x0 * y0 + x1 * y1;
#pragma unroll
        for (int o = 16; o; o >>= 1) {
            svv += __shfl_down_sync(0xffffffffu, svv, o);
            saa += __shfl_down_sync(0xffffffffu, saa, o);
            sva += __shfl_down_sync(0xffffffffu, sva, o);
        }
        if (lane == 0) { g_vv[row] = svv; g_aa[row] = saa; g_va[row] = sva; }
    } else {
        const int b = blk - 16384;
        const int bh = b >> 4;
        const int s0 = (b & 15) * 64;
        const float* vp = g_vh + (size_t)(bh * 1024 + s0) * 64;
        const float* vp2 = g_v2 + (size_t)(bh * 1024 + s0) * 64;
#pragma unroll
        for (int u = 0; u < 4; u++) {
            int id = tid + u * 256;
            int r = id >> 4, c4 = (id & 15) * 4;
            float4 x = *(const float4*)(vp + r * 64 + c4);
            float4 y = *(const float4*)(vp2 + r * 64 + c4);
            tile[r * 65 + c4 + 0] = x.x + y.x;
            tile[r * 65 + c4 + 1] = x.y + y.y;
            tile[r * 65 + c4 + 2] = x.z + y.z;
            tile[r * 65 + c4 + 3] = x.w + y.w;
        }
        __syncthreads();
#pragma unroll
        for (int u = 0; u < 8; u++) {
            int id = tid + u * 256;
            int d = id >> 5, sp = id & 31;
            float x0 = tile[(2 * sp) * 65 + d];
            float x1 = tile[(2 * sp + 1) * 65 + d];
            size_t off = ((size_t)(bh * 64 + d) * 1024 + s0 + 2 * sp);
            *(uint32_t*)(g_vthb + off) = pk_hi(x0, x1);
            *(uint32_t*)(g_vtlb + off) = pk_lo(x0, x1);
        }
    }
}

// =====================================================================
// flash_mma: R13 best version — 128 q-rows, 256 thr, double-buffered,
//            fixed-max softmax, ks-outer MMA loops
// =====================================================================
#define FK (64 * GP)
#define FL_SMEM_B (2 * 6 * FK * 2)

__global__ void __launch_bounds__(256) flash_mma()
{
    extern __shared__ __nv_bfloat16 fs[];
    const uint32_t sbs = smem_u32(fs);

    const int tid = threadIdx.x;
    const int wid = tid >> 5, lane = tid & 31;
    const int lq = lane >> 2;
    const int lk = (lane & 3) * 2;
    const int bh = blockIdx.y;
    const int l0 = blockIdx.x * 128;
    const int bhS = bh * 1024;

    uint32_t qh[4][4], ql[4][4];
    {
        const float* q0 = g_qh + (size_t)(bhS + l0 + wid * 16 + lq) * 64;
        const float* q8 = q0 + 8 * 64;
#pragma unroll
        for (int ks = 0; ks < 4; ks++) {
            float2 x00 = *(const float2*)(q0 + ks * 16 + lk);
            float2 x10 = *(const float2*)(q8 + ks * 16 + lk);
            float2 x01 = *(const float2*)(q0 + ks * 16 + lk + 8);
            float2 x11 = *(const float2*)(q8 + ks * 16 + lk + 8);
            qh[ks][0] = pk_hi(x00.x, x00.y); ql[ks][0] = pk_lo(x00.x, x00.y);
            qh[ks][1] = pk_hi(x10.x, x10.y); ql[ks][1] = pk_lo(x10.x, x10.y);
            qh[ks][2] = pk_hi(x01.x, x01.y); ql[ks][2] = pk_lo(x01.x, x01.y);
            qh[ks][3] = pk_hi(x11.x, x11.y); ql[ks][3] = pk_lo(x11.x, x11.y);
        }
    }
    const float ll0 = g_ll[bhS + l0 + wid * 16 + lq];
    const float ll1 = g_ll[bhS + l0 + wid * 16 + lq + 8];

    float ls0 = 0.f, ls1 = 0.f;
    float o[8][4];
#pragma unroll
    for (int dt = 0; dt < 8; dt++)
#pragma unroll
        for (int c = 0; c < 4; c++) o[dt][c] = 0.f;

    auto issue = [&](int buf, int s0) {
        const uint32_t dbase = sbs + (uint32_t)buf * (6 * FK * 2);
#pragma unroll
        for (int t = 0; t < 12; t++) {
            int cid = tid + t * 256;
            int tile = cid >> 9;
            int r = (cid >> 3) & 63;
            int c = cid & 7;
            const __nv_bfloat16* src;
            if (tile == 0)      src = g_k1hb + ((size_t)(bhS + s0 + r) * 64 + c * 8);
            else if (tile == 1) src = g_k1lb + ((size_t)(bhS + s0 + r) * 64 + c * 8);
            else if (tile == 2) src = g_k2hb + ((size_t)(bhS + s0 + r) * 64 + c * 8);
            else if (tile == 3) src = g_k2lb + ((size_t)(bhS + s0 + r) * 64 + c * 8);
            else if (tile == 4) src = g_vthb + ((size_t)(bh * 64 + r) * 1024 + s0 + c * 8);
            else                src = g_vtlb + ((size_t)(bh * 64 + r) * 1024 + s0 + c * 8);
            cpa16(dbase + (uint32_t)(tile * FK + r * GP + c * 8) * 2, src);
        }
        asm volatile("cp.async.commit_group;");
    };

    issue(0, 0);

    for (int it = 0; it < 16; it++) {
        const int buf = it & 1;
        const int s0 = it * 64;
        if (it < 15) issue(buf ^ 1, s0 + 64);
        if (it < 15) asm volatile("cp.async.wait_group 1;");
        else         asm volatile("cp.async.wait_group 0;");
        __syncthreads();

        const __nv_bfloat16* Kb  = fs + buf * (6 * FK);
        const __nv_bfloat16* K1h = Kb;
        const __nv_bfloat16* K1l = Kb + FK;
        const __nv_bfloat16* K2h = Kb + 2 * FK;
        const __nv_bfloat16* K2l = Kb + 3 * FK;
        const __nv_bfloat16* VTh = Kb + 4 * FK;
        const __nv_bfloat16* VTl = Kb + 5 * FK;

        float lv[8][4], la[8][4];
#pragma unroll
        for (int nt = 0; nt < 8; nt++)
#pragma unroll
            for (int c = 0; c < 4; c++) { lv[nt][c] = 0.f; la[nt][c] = 0.f; }

#pragma unroll
        for (int ks = 0; ks < 4; ks++) {
#pragma unroll
            for (int nt = 0; nt < 8; nt++) {
                const __nv_bfloat16* b1h = K1h + (nt * 8 + lq) * GP + ks * 16 + lk;
                uint32_t h0 = *(const uint32_t*)b1h;
                uint32_t h1 = *(const uint32_t*)(b1h + 8);
                const __nv_bfloat16* b1l = K1l + (nt * 8 + lq) * GP + ks * 16 + lk;
                uint32_t l0_ = *(const uint32_t*)b1l;
                uint32_t l1_ = *(const uint32_t*)(b1l + 8);
                mma16816(lv[nt], qh[ks][0], qh[ks][1], qh[ks][2], qh[ks][3], h0, h1);
                mma16816(lv[nt], qh[ks][0], qh[ks][1], qh[ks][2], qh[ks][3], l0_, l1_);
                mma16816(lv[nt], ql[ks][0], ql[ks][1], ql[ks][2], ql[ks][3], h0, h1);
                const __nv_bfloat16* b2h = K2h + (nt * 8 + lq) * GP + ks * 16 + lk;
                uint32_t g0 = *(const uint32_t*)b2h;
                uint32_t g1 = *(const uint32_t*)(b2h + 8);
                const __nv_bfloat16* b2l = K2l + (nt * 8 + lq) * GP + ks * 16 + lk;
                uint32_t e0 = *(const uint32_t*)b2l;
                uint32_t e1 = *(const uint32_t*)(b2l + 8);
                mma16816(la[nt], qh[ks][0], qh[ks][1], qh[ks][2], qh[ks][3], g0, g1);
                mma16816(la[nt], qh[ks][0], qh[ks][1], qh[ks][2], qh[ks][3], e0, e1);
                mma16816(la[nt], ql[ks][0], ql[ks][1], ql[ks][2], ql[ks][3], g0, g1);
            }
        }

        // gram-det -> p = exp(-sqrt(det)) (fixed max 0)
#pragma unroll
        for (int nt = 0; nt < 8; nt++) {
            float2 vv2 = *(const float2*)(g_vv + bhS + s0 + nt * 8 + lk);
            float2 aa2 = *(const float2*)(g_aa + bhS + s0 + nt * 8 + lk);
            float2 va2 = *(const float2*)(g_va + bhS + s0 + nt * 8 + lk);
            float g2x = vv2.x * aa2.x - va2.x * va2.x;
            float g2y = vv2.y * aa2.y - va2.y * va2.y;
            {
                float LV = lv[nt][0], LA = la[nt][0];
                float det = ll0 * g2x - LV * (LV * aa2.x - LA * va2.x) + LA * (LV * va2.x - LA * vv2.x);
                float p = pexp_negsqrt(det);
                lv[nt][0] = p; ls0 += p;
            }
            {
                float LV = lv[nt][1], LA = la[nt][1];
                float det = ll0 * g2y - LV * (LV * aa2.y - LA * va2.y) + LA * (LV * va2.y - LA * vv2.y);
                float p = pexp_negsqrt(det);
                lv[nt][1] = p; ls0 += p;
            }
            {
                float LV = lv[nt][2], LA = la[nt][2];
                float det = ll1 * g2x - LV * (LV * aa2.x - LA * va2.x) + LA * (LV * va2.x - LA * vv2.x);
                float p = pexp_negsqrt(det);
                lv[nt][2] = p; ls1 += p;
            }
            {
                float LV = lv[nt][3], LA = la[nt][3];
                float det = ll1 * g2y - LV * (LV * aa2.y - LA * va2.y) + LA * (LV * va2.y - LA * vv2.y);
                float p = pexp_negsqrt(det);
                lv[nt][3] = p; ls1 += p;
            }
        }

        uint32_t ph[4][4], pl[4][4];
#pragma unroll
        for (int ks = 0; ks < 4; ks++) {
            ph[ks][0] = pk_hi(lv[2 * ks][0], lv[2 * ks][1]);
            pl[ks][0] = pk_lo(lv[2 * ks][0], lv[2 * ks][1]);
            ph[ks][1] = pk_hi(lv[2 * ks][2], lv[2 * ks][3]);
            pl[ks][1] = pk_lo(lv[2 * ks][2], lv[2 * ks][3]);
            ph[ks][2] = pk_hi(lv[2 * ks + 1][0], lv[2 * ks + 1][1]);
            pl[ks][2] = pk_lo(lv[2 * ks + 1][0], lv[2 * ks + 1][1]);
            ph[ks][3] = pk_hi(lv[2 * ks + 1][2], lv[2 * ks + 1][3]);
            pl[ks][3] = pk_lo(lv[2 * ks + 1][2], lv[2 * ks + 1][3]);
        }

#pragma unroll
        for (int ks = 0; ks < 4; ks++) {
#pragma unroll
            for (int dt = 0; dt < 8; dt++) {
                const __nv_bfloat16* vh = VTh + (dt * 8 + lq) * GP + ks * 16 + lk;
                uint32_t vh0 = *(const uint32_t*)vh;
                uint32_t vh1 = *(const uint32_t*)(vh + 8);
                const __nv_bfloat16* vl = VTl + (dt * 8 + lq) * GP + ks * 16 + lk;
                uint32_t vl0 = *(const uint32_t*)vl;
                uint32_t vl1 = *(const uint32_t*)(vl + 8);
                mma16816(o[dt], ph[ks][0], ph[ks][1], ph[ks][2], ph[ks][3], vh0, vh1);
                mma16816(o[dt], ph[ks][0], ph[ks][1], ph[ks][2], ph[ks][3], vl0, vl1);
                mma16816(o[dt], pl[ks][0], pl[ks][1], pl[ks][2], pl[ks][3], vh0, vh1);
            }
        }
        __syncthreads();
    }

    ls0 += __shfl_xor_sync(0xffffffffu, ls0, 1);
    ls0 += __shfl_xor_sync(0xffffffffu, ls0, 2);
    ls1 += __shfl_xor_sync(0xffffffffu, ls1, 1);
    ls1 += __shfl_xor_sync(0xffffffffu, ls1, 2);

    const float inv0 = frcp_pos(ls0);
    const float inv1 = frcp_pos(ls1);
    const int bi = bh >> 3, h = bh & 7;
    const int r0 = l0 + wid * 16 + lq;
#pragma unroll
    for (int dt = 0; dt < 8; dt++) {
        int d = dt * 8 + lk;
        float a0 = o[dt][0] * inv0, a1 = o[dt][1] * inv0;
        float b0 = o[dt][2] * inv1, b1 = o[dt][3] * inv1;
        size_t off0 = (size_t)(r0 * 8 + bi) * 512 + h * 64 + d;
        size_t off1 = (size_t)((r0 + 8) * 8 + bi) * 512 + h * 64 + d;
        *(uint32_t*)(g_aoh + off0) = pk_hi(a0, a1);
        *(uint32_t*)(g_aol + off0) = pk_lo(a0, a1);
        *(uint32_t*)(g_aoh + off1) = pk_hi(b0, b1);
        *(uint32_t*)(g_aol + off1) = pk_lo(b0, b1);
    }
}

// ---------------- launch ----------------
extern "C" void kernel_launch(void* const* d_in, const int* in_sizes, int n_in,
                              void* d_out, int out_size) {
    const float* query = (const float*)d_in[0];
    const float* mod1  = (const float*)d_in[1];
    const float* mod2  = (const float*)d_in[2];
    const float* Wq  = (const float*)d_in[3];  const float* bq  = (const float*)d_in[4];
    const float* Wk1 = (const float*)d_in[5];  const float* bk1 = (const float*)d_in[6];
    const float* Wk2 = (const float*)d_in[7];  const float* bk2 = (const float*)d_in[8];
    const float* Wv1 = (const float*)d_in[9];  const float* bv1 = (const float*)d_in[10];
    const float* Wv2 = (const float*)d_in[11]; const float* bv2 = (const float*)d_in[12];
    const float* Wg1 = (const float*)d_in[13]; const float* bg1 = (const float*)d_in[14];
    const float* Wg2 = (const float*)d_in[15]; const float* bg2 = (const float*)d_in[16];
    const float* Wo  = (const float*)d_in[17]; const float* bo  = (const float*)d_in[18];
    float* out = (float*)d_out;

    cudaFuncSetAttribute(proj3_cp,    cudaFuncAttributeMaxDynamicSharedMemorySize, PJ_SMEM_B);
    cudaFuncSetAttribute(proj_out_cp, cudaFuncAttributeMaxDynamicSharedMemorySize, PJ_SMEM_B);
    cudaFuncSetAttribute(projvg_cp,   cudaFuncAttributeMaxDynamicSharedMemorySize, VG_SMEM_B);
    cudaFuncSetAttribute(flash_mma,   cudaFuncAttributeMaxDynamicSharedMemorySize, FL_SMEM_B);

    dim3 pb(256);
    prep_all<<<14336, pb>>>(query, mod1, mod2,
                            Wq, Wk1, Wk2, Wv1, Wv2, Wg1, Wg2, Wo);
    proj3_cp<<<dim3(64, 4, 3), pb, PJ_SMEM_B>>>(bq, bk1, bk2);
    projvg_cp<<<dim3(64, 4, 2), pb, VG_SMEM_B>>>(bv1, bg1, bv2, bg2);
    norm_prep<<<17408, pb>>>();
    flash_mma<<<dim3(8, 64), 256, FL_SMEM_B>>>();
    proj_out_cp<<<dim3(64, 4), pb, PJ_SMEM_B>>>(bo, out);
}

// round 17
// speedup vs baseline: 1.0613x; 1.0404x over previous
#include <cuda_runtime.h>
#include <cuda_bf16.h>
#include <cstdint>

#define CL   1024
#define CS   1024
#define CB   8
#define CE   512
#define CH   8
#define CDH  64
#define CBH  64
#define CM   8192
#define CK   512
#define WSZ  (CE * CK)

// ---------------- device scratch ----------------
__device__ __align__(128) float g_qh [CBH * CL * CDH];
__device__ __align__(128) float g_k1h[CBH * CS * CDH];
__device__ __align__(128) float g_k2h[CBH * CS * CDH];
__device__ __align__(128) float g_vh [CBH * CS * CDH];
__device__ __align__(128) float g_v2 [CBH * CS * CDH];
__device__ __align__(128) float g_ll [CBH * CL];
__device__ __align__(128) float g_vv [CBH * CS];
__device__ __align__(128) float g_aa [CBH * CS];
__device__ __align__(128) float g_va [CBH * CS];
// bf16 hi/lo operand caches
__device__ __align__(128) __nv_bfloat16 g_k1hb[CBH * CS * CDH];
__device__ __align__(128) __nv_bfloat16 g_k1lb[CBH * CS * CDH];
__device__ __align__(128) __nv_bfloat16 g_k2hb[CBH * CS * CDH];
__device__ __align__(128) __nv_bfloat16 g_k2lb[CBH * CS * CDH];
__device__ __align__(128) __nv_bfloat16 g_vthb[CBH * CDH * CS];   // [bh][d][s]
__device__ __align__(128) __nv_bfloat16 g_vtlb[CBH * CDH * CS];
// pre-split GEMM operands
__device__ __align__(128) __nv_bfloat16 g_qryh[CM * CK];
__device__ __align__(128) __nv_bfloat16 g_qryl[CM * CK];
__device__ __align__(128) __nv_bfloat16 g_m1h [CM * CK];
__device__ __align__(128) __nv_bfloat16 g_m1l [CM * CK];
__device__ __align__(128) __nv_bfloat16 g_m2h [CM * CK];
__device__ __align__(128) __nv_bfloat16 g_m2l [CM * CK];
__device__ __align__(128) __nv_bfloat16 g_wh  [8 * WSZ];
__device__ __align__(128) __nv_bfloat16 g_wl  [8 * WSZ];
__device__ __align__(128) __nv_bfloat16 g_aoh [CM * CE];
__device__ __align__(128) __nv_bfloat16 g_aol [CM * CE];

// ---------------- MUFU-free math ----------------
__device__ __forceinline__ float fexp(float x) {
    float t = x * 1.4426950408889634f;
    t = fminf(fmaxf(t, -126.0f), 126.0f);
    int i = __float2int_rn(t);
    float u = (t - (float)i) * 0.6931471805599453f;
    float p = 1.3888889e-3f;
    p = fmaf(p, u, 8.3333333e-3f);
    p = fmaf(p, u, 4.1666667e-2f);
    p = fmaf(p, u, 1.6666667e-1f);
    p = fmaf(p, u, 0.5f);
    p = fmaf(p, u, 1.0f);
    p = fmaf(p, u, 1.0f);
    return p * __int_as_float((i + 127) << 23);
}
__device__ __forceinline__ float frcp_pos(float x) {
    float y = __int_as_float(0x7EF127EAu - __float_as_int(x));
    y = y * (2.0f - x * y);
    y = y * (2.0f - x * y);
    y = y * (2.0f - x * y);
    return y;
}
// p = exp(-sqrt(max(det,1e-8))) — fused, MUFU-free, scores are always <= 0
__device__ __forceinline__ float pexp_negsqrt(float det) {
    det = fmaxf(det, 1e-8f);
    float y = __int_as_float(0x5f3759df - (__float_as_int(det) >> 1));
    y = y * fmaf(-0.5f * det, y * y, 1.5f);
    y = y * fmaf(-0.5f * det, y * y, 1.5f);
    float s = det * y;                                  // sqrt(det)
    float t = fmaxf(s * -1.4426950408889634f, -126.0f); // always <= 0
    int i = __float2int_rn(t);
    float u = (t - (float)i) * 0.6931471805599453f;
    float p = 8.3333333e-3f;
    p = fmaf(p, u, 4.1666667e-2f);
    p = fmaf(p, u, 1.6666667e-1f);
    p = fmaf(p, u, 0.5f);
    p = fmaf(p, u, 1.0f);
    p = fmaf(p, u, 1.0f);
    return p * __int_as_float((i + 127) << 23);
}

// ---------------- mma.sync bf16 helper ----------------
__device__ __forceinline__ void mma16816(float* c,
    uint32_t a0, uint32_t a1, uint32_t a2, uint32_t a3,
    uint32_t b0, uint32_t b1)
{
    asm volatile(
        "mma.sync.aligned.m16n8k16.row.col.f32.bf16.bf16.f32 "
        "{%0,%1,%2,%3},{%4,%5,%6,%7},{%8,%9},{%0,%1,%2,%3};"
        : "+f"(c[0]), "+f"(c[1]), "+f"(c[2]), "+f"(c[3])
        : "r"(a0), "r"(a1), "r"(a2), "r"(a3), "r"(b0), "r"(b1));
}

#define GP 72
#define TSZ (128 * GP)
__device__ __forceinline__ uint32_t pkbf(__nv_bfloat16 a, __nv_bfloat16 b) {
    __nv_bfloat162 t(a, b);
    return *reinterpret_cast<uint32_t*>(&t);
}
__device__ __forceinline__ uint32_t pk_hi(float x, float y) {
    return pkbf(__float2bfloat16(x), __float2bfloat16(y));
}
__device__ __forceinline__ uint32_t pk_lo(float x, float y) {
    __nv_bfloat16 hx = __float2bfloat16(x), hy = __float2bfloat16(y);
    return pkbf(__float2bfloat16(x - __bfloat162float(hx)),
                __float2bfloat16(y - __bfloat162float(hy)));
}
__device__ __forceinline__ uint32_t smem_u32(const void* p) {
    uint32_t a;
    asm("{ .reg .u64 t; cvta.to.shared.u64 t, %1; cvt.u32.u64 %0, t; }" : "=r"(a) : "l"(p));
    return a;
}
__device__ __forceinline__ void cpa16(uint32_t dst, const void* src) {
    asm volatile("cp.async.cg.shared.global [%0], [%1], 16;" :: "r"(dst), "l"(src));
}

// ---------------- prep_all: activations (3x) + weights (8x) in one launch ----------------
__global__ void __launch_bounds__(256)
prep_all(const float* __restrict__ q, const float* __restrict__ m1,
         const float* __restrict__ m2,
         const float* __restrict__ w0, const float* __restrict__ w1,
         const float* __restrict__ w2, const float* __restrict__ w3,
         const float* __restrict__ w4, const float* __restrict__ w5,
         const float* __restrict__ w6, const float* __restrict__ w7)
{
    const int b = blockIdx.x;
    if (b < 12288) {
        const int z = b >> 12;
        const int bx = b & 4095;
        const float* src = (z == 0) ? q : (z == 1) ? m1 : m2;
        __nv_bfloat16* H = (z == 0) ? g_qryh : (z == 1) ? g_m1h : g_m2h;
        __nv_bfloat16* L = (z == 0) ? g_qryl : (z == 1) ? g_m1l : g_m2l;
        size_t i4 = (size_t)bx * 256 + threadIdx.x;
        float4 x = ((const float4*)src)[i4];
        ((uint2*)H)[i4] = make_uint2(pk_hi(x.x, x.y), pk_hi(x.z, x.w));
        ((uint2*)L)[i4] = make_uint2(pk_lo(x.x, x.y), pk_lo(x.z, x.w));
    } else {
        const int zz = (b - 12288) >> 8;
        const int bx = (b - 12288) & 255;
        const float* src;
        switch (zz) {
            case 0: src = w0; break; case 1: src = w1; break;
            case 2: src = w2; break; case 3: src = w3; break;
            case 4: src = w4; break; case 5: src = w5; break;
            case 6: src = w6; break; default: src = w7; break;
        }
        size_t i4 = (size_t)bx * 256 + threadIdx.x;
        float4 x = ((const float4*)src)[i4];
        ((uint2*)(g_wh + (size_t)zz * WSZ))[i4] = make_uint2(pk_hi(x.x, x.y), pk_hi(x.z, x.w));
        ((uint2*)(g_wl + (size_t)zz * WSZ))[i4] = make_uint2(pk_lo(x.x, x.y), pk_lo(x.z, x.w));
    }
}

// =====================================================================
// proj_fused: grid.z in [0,5).
//   z=0..2 : q/k1/k2 projection (proj3 body)
//   z=3..4 : gated value projection, mod = z-3 (projvg body)
// smem request = VG size (216 KB); both paths run 1 CTA/SM either way.
// =====================================================================
#define PJ_STAGE (4 * TSZ)
#define VG_STAGE (6 * TSZ)
#define FUSED_SMEM_B (2 * VG_STAGE * 2)

__global__ void __launch_bounds__(256)
proj_fused(const float* __restrict__ bq, const float* __restrict__ bk1,
           const float* __restrict__ bk2,
           const float* __restrict__ bv1, const float* __restrict__ bg1,
           const float* __restrict__ bv2, const float* __restrict__ bg2)
{
    extern __shared__ __nv_bfloat16 fs[];
    const uint32_t sbs = smem_u32(fs);
    const int z = blockIdx.z;

    const int tid = threadIdx.x;
    const int wid = tid >> 5, lane = tid & 31;
    const int wm = wid >> 2, wn = wid & 3;
    const int m0 = blockIdx.x * 128;
    const int n0 = blockIdx.y * 128;
    const int lq = lane >> 2;
    const int lk = (lane & 3) * 2;

    if (z < 3) {
        // ---------------- proj3 body ----------------
        const __nv_bfloat16* Ah_g = (z == 0) ? g_qryh : (z == 1) ? g_m1h : g_m2h;
        const __nv_bfloat16* Al_g = (z == 0) ? g_qryl : (z == 1) ? g_m1l : g_m2l;
        const __nv_bfloat16* Wh_g = g_wh + (size_t)z * WSZ;
        const __nv_bfloat16* Wl_g = g_wl + (size_t)z * WSZ;
        const float* bias = (z == 0) ? bq : (z == 1) ? bk1 : bk2;
        float* C = (z == 0) ? g_qh : (z == 1) ? g_k1h : g_k2h;
        __nv_bfloat16* CHo = (z == 1) ? g_k1hb : g_k2hb;
        __nv_bfloat16* CLo = (z == 1) ? g_k1lb : g_k2lb;

        auto issue = [&](int buf, int k0) {
            const uint32_t dbase = sbs + (uint32_t)buf * (PJ_STAGE * 2);
#pragma unroll
            for (int t = 0; t < 16; t++) {
                int cid = tid + t * 256;
                int tile = cid >> 10;
                int r = (cid >> 3) & 127;
                int c = cid & 7;
                const __nv_bfloat16* src;
                if (tile == 0)      src = Ah_g + (size_t)(m0 + r) * CK + k0 + c * 8;
                else if (tile == 1) src = Al_g + (size_t)(m0 + r) * CK + k0 + c * 8;
                else if (tile == 2) src = Wh_g + (size_t)(n0 + r) * CK + k0 + c * 8;
                else                src = Wl_g + (size_t)(n0 + r) * CK + k0 + c * 8;
                cpa16(dbase + (uint32_t)(tile * TSZ + r * GP + c * 8) * 2, src);
            }
            asm volatile("cp.async.commit_group;");
        };

        float acc[4][4][4];
#pragma unroll
        for (int a = 0; a < 4; a++)
#pragma unroll
            for (int b = 0; b < 4; b++)
#pragma unroll
                for (int c = 0; c < 4; c++) acc[a][b][c] = 0.f;

        issue(0, 0);
        for (int blk = 0; blk < 8; blk++) {
            const int buf = blk & 1;
            if (blk < 7) issue(buf ^ 1, (blk + 1) * 64);
            if (blk < 7) asm volatile("cp.async.wait_group 1;");
            else         asm volatile("cp.async.wait_group 0;");
            __syncthreads();

            const __nv_bfloat16* Ah = fs + buf * PJ_STAGE;
            const __nv_bfloat16* Al = Ah + TSZ;
            const __nv_bfloat16* Wh = Ah + 2 * TSZ;
            const __nv_bfloat16* Wl = Ah + 3 * TSZ;

#pragma unroll
            for (int ks = 0; ks < 4; ks++) {
                uint32_t ah[4][4], al[4][4];
#pragma unroll
                for (int mt = 0; mt < 4; mt++) {
                    const __nv_bfloat16* ar = Ah + (wm * 64 + mt * 16 + lq) * GP + ks * 16 + lk;
                    ah[mt][0] = *(const uint32_t*)ar;
                    ah[mt][1] = *(const uint32_t*)(ar + 8 * GP);
                    ah[mt][2] = *(const uint32_t*)(ar + 8);
                    ah[mt][3] = *(const uint32_t*)(ar + 8 * GP + 8);
                    const __nv_bfloat16* al_ = Al + (wm * 64 + mt * 16 + lq) * GP + ks * 16 + lk;
                    al[mt][0] = *(const uint32_t*)al_;
                    al[mt][1] = *(const uint32_t*)(al_ + 8 * GP);
                    al[mt][2] = *(const uint32_t*)(al_ + 8);
                    al[mt][3] = *(const uint32_t*)(al_ + 8 * GP + 8);
                }
#pragma unroll
                for (int nt = 0; nt < 4; nt++) {
                    const __nv_bfloat16* bh = Wh + (wn * 32 + nt * 8 + lq) * GP + ks * 16 + lk;
                    uint32_t bh0 = *(const uint32_t*)bh;
                    uint32_t bh1 = *(const uint32_t*)(bh + 8);
                    const __nv_bfloat16* bl = Wl + (wn * 32 + nt * 8 + lq) * GP + ks * 16 + lk;
                    uint32_t bl0 = *(const uint32_t*)bl;
                    uint32_t bl1 = *(const uint32_t*)(bl + 8);
#pragma unroll
                    for (int mt = 0; mt < 4; mt++) {
                        mma16816(acc[mt][nt], ah[mt][0], ah[mt][1], ah[mt][2], ah[mt][3], bh0, bh1);
                        mma16816(acc[mt][nt], ah[mt][0], ah[mt][1], ah[mt][2], ah[mt][3], bl0, bl1);
                        mma16816(acc[mt][nt], al[mt][0], al[mt][1], al[mt][2], al[mt][3], bh0, bh1);
                    }
                }
            }
            __syncthreads();
        }

        const float scale = (z == 0) ? 0.125f : 1.0f;
#pragma unroll
        for (int mt = 0; mt < 4; mt++) {
#pragma unroll
            for (int nt = 0; nt < 4; nt++) {
                int row = m0 + wm * 64 + mt * 16 + lq;
                int col = n0 + wn * 32 + nt * 8 + lk;
                float b0 = bias[col], b1 = bias[col + 1];
                int h = col >> 6, d = col & 63;
#pragma unroll
                for (int half = 0; half < 2; half++) {
                    int r = row + half * 8;
                    int t = r >> 3, bi = r & 7;
                    float2 v;
                    v.x = (acc[mt][nt][half * 2 + 0] + b0) * scale;
                    v.y = (acc[mt][nt][half * 2 + 1] + b1) * scale;
                    size_t off = ((size_t)(bi * 8 + h) * 1024 + t) * 64 + d;
                    *(float2*)(C + off) = v;
                    if (z >= 1) {
                        *(uint32_t*)(CHo + off) = pk_hi(v.x, v.y);
                        *(uint32_t*)(CLo + off) = pk_lo(v.x, v.y);
                    }
                }
            }
        }
    } else {
        // ---------------- projvg body ----------------
        const int mod = z - 3;
        const __nv_bfloat16* Ah_g = mod ? g_m2h : g_m1h;
        const __nv_bfloat16* Al_g = mod ? g_m2l : g_m1l;
        const __nv_bfloat16* Vh_g = g_wh + (size_t)(3 + mod) * WSZ;
        const __nv_bfloat16* Vl_g = g_wl + (size_t)(3 + mod) * WSZ;
        const __nv_bfloat16* Gh_g = g_wh + (size_t)(5 + mod) * WSZ;
        const __nv_bfloat16* Gl_g = g_wl + (size_t)(5 + mod) * WSZ;
        const float* bv = mod ? bv2 : bv1;
        const float* bg = mod ? bg2 : bg1;
        float* Cdst = mod ? g_v2 : g_vh;

        auto issue = [&](int buf, int k0) {
            const uint32_t dbase = sbs + (uint32_t)buf * (VG_STAGE * 2);
#pragma unroll
            for (int t = 0; t < 24; t++) {
                int cid = tid + t * 256;
                int tile = cid >> 10;
                int r = (cid >> 3) & 127;
                int c = cid & 7;
                const __nv_bfloat16* src;
                if (tile == 0)      src = Ah_g + (size_t)(m0 + r) * CK + k0 + c * 8;
                else if (tile == 1) src = Al_g + (size_t)(m0 + r) * CK + k0 + c * 8;
                else if (tile == 2) src = Vh_g + (size_t)(n0 + r) * CK + k0 + c * 8;
                else if (tile == 3) src = Vl_g + (size_t)(n0 + r) * CK + k0 + c * 8;
                else if (tile == 4) src = Gh_g + (size_t)(n0 + r) * CK + k0 + c * 8;
                else                src = Gl_g + (size_t)(n0 + r) * CK + k0 + c * 8;
                cpa16(dbase + (uint32_t)(tile * TSZ + r * GP + c * 8) * 2, src);
            }
            asm volatile("cp.async.commit_group;");
        };

        float av_[4][4][4], ag_[4][4][4];
#pragma unroll
        for (int a = 0; a < 4; a++)
#pragma unroll
            for (int b = 0; b < 4; b++)
#pragma unroll
                for (int c = 0; c < 4; c++) { av_[a][b][c] = 0.f; ag_[a][b][c] = 0.f; }

        issue(0, 0);
        for (int blk = 0; blk < 8; blk++) {
            const int buf = blk & 1;
            if (blk < 7) issue(buf ^ 1, (blk + 1) * 64);
            if (blk < 7) asm volatile("cp.async.wait_group 1;");
            else         asm volatile("cp.async.wait_group 0;");
            __syncthreads();

            const __nv_bfloat16* Ah = fs + buf * VG_STAGE;
            const __nv_bfloat16* Al = Ah + TSZ;
            const __nv_bfloat16* Vh = Ah + 2 * TSZ;
            const __nv_bfloat16* Vl = Ah + 3 * TSZ;
            const __nv_bfloat16* Gh = Ah + 4 * TSZ;
            const __nv_bfloat16* Gl = Ah + 5 * TSZ;

#pragma unroll
            for (int ks = 0; ks < 4; ks++) {
                uint32_t ah[4][4], al[4][4];
#pragma unroll
                for (int mt = 0; mt < 4; mt++) {
                    const __nv_bfloat16* ar = Ah + (wm * 64 + mt * 16 + lq) * GP + ks * 16 + lk;
                    ah[mt][0] = *(const uint32_t*)ar;
                    ah[mt][1] = *(const uint32_t*)(ar + 8 * GP);
                    ah[mt][2] = *(const uint32_t*)(ar + 8);
                    ah[mt][3] = *(const uint32_t*)(ar + 8 * GP + 8);
                    const __nv_bfloat16* al_ = Al + (wm * 64 + mt * 16 + lq) * GP + ks * 16 + lk;
                    al[mt][0] = *(const uint32_t*)al_;
                    al[mt][1] = *(const uint32_t*)(al_ + 8 * GP);
                    al[mt][2] = *(const uint32_t*)(al_ + 8);
                    al[mt][3] = *(const uint32_t*)(al_ + 8 * GP + 8);
                }
#pragma unroll
                for (int nt = 0; nt < 4; nt++) {
                    const __nv_bfloat16* vh = Vh + (wn * 32 + nt * 8 + lq) * GP + ks * 16 + lk;
                    uint32_t vh0 = *(const uint32_t*)vh;
                    uint32_t vh1 = *(const uint32_t*)(vh + 8);
                    const __nv_bfloat16* vl = Vl + (wn * 32 + nt * 8 + lq) * GP + ks * 16 + lk;
                    uint32_t vl0 = *(const uint32_t*)vl;
                    uint32_t vl1 = *(const uint32_t*)(vl + 8);
                    const __nv_bfloat16* gh = Gh + (wn * 32 + nt * 8 + lq) * GP + ks * 16 + lk;
                    uint32_t gh0 = *(const uint32_t*)gh;
                    uint32_t gh1 = *(const uint32_t*)(gh + 8);
                    const __nv_bfloat16* gl = Gl + (wn * 32 + nt * 8 + lq) * GP + ks * 16 + lk;
                    uint32_t gl0 = *(const uint32_t*)gl;
                    uint32_t gl1 = *(const uint32_t*)(gl + 8);
#pragma unroll
                    for (int mt = 0; mt < 4; mt++) {
                        mma16816(av_[mt][nt], ah[mt][0], ah[mt][1], ah[mt][2], ah[mt][3], vh0, vh1);
                        mma16816(av_[mt][nt], ah[mt][0], ah[mt][1], ah[mt][2], ah[mt][3], vl0, vl1);
                        mma16816(av_[mt][nt], al[mt][0], al[mt][1], al[mt][2], al[mt][3], vh0, vh1);
                        mma16816(ag_[mt][nt], ah[mt][0], ah[mt][1], ah[mt][2], ah[mt][3], gh0, gh1);
                        mma16816(ag_[mt][nt], ah[mt][0], ah[mt][1], ah[mt][2], ah[mt][3], gl0, gl1);
                        mma16816(ag_[mt][nt], al[mt][0], al[mt][1], al[mt][2], al[mt][3], gh0, gh1);
                    }
                }
            }
            __syncthreads();
        }

#pragma unroll
        for (int mt = 0; mt < 4; mt++) {
#pragma unroll
            for (int nt = 0; nt < 4; nt++) {
                int row = m0 + wm * 64 + mt * 16 + lq;
                int col = n0 + wn * 32 + nt * 8 + lk;
                float bv0 = bv[col], bv1_ = bv[col + 1];
                float bg0 = bg[col], bg1_ = bg[col + 1];
                int h = col >> 6, d = col & 63;
#pragma unroll
                for (int half = 0; half < 2; half++) {
                    int r = row + half * 8;
                    int t = r >> 3, bi = r & 7;
                    float vx0 = av_[mt][nt][half * 2 + 0] + bv0;
                    float vx1 = av_[mt][nt][half * 2 + 1] + bv1_;
                    float gx0 = ag_[mt][nt][half * 2 + 0] + bg0;
                    float gx1 = ag_[mt][nt][half * 2 + 1] + bg1_;
                    float2 v;
                    v.x = vx0 * frcp_pos(1.0f + fexp(-gx0));
                    v.y = vx1 * frcp_pos(1.0f + fexp(-gx1));
                    *(float2*)(Cdst + ((size_t)(bi * 8 + h) * 1024 + t) * 64 + d) = v;
                }
            }
        }
    }
}

// =====================================================================
// proj_out_cp: out = ao @ Wo^T + bo (unchanged)
// =====================================================================
#define PJ_SMEM_B (2 * PJ_STAGE * 2)

__global__ void __launch_bounds__(256)
proj_out_cp(const float* __restrict__ bias, float* __restrict__ C)
{
    extern __shared__ __nv_bfloat16 fs[];
    const uint32_t sbs = smem_u32(fs);
    const __nv_bfloat16* Wh_g = g_wh + (size_t)7 * WSZ;
    const __nv_bfloat16* Wl_g = g_wl + (size_t)7 * WSZ;

    const int tid = threadIdx.x;
    const int wid = tid >> 5, lane = tid & 31;
    const int wm = wid >> 2, wn = wid & 3;
    const int m0 = blockIdx.x * 128;
    const int n0 = blockIdx.y * 128;
    const int lq = lane >> 2;
    const int lk = (lane & 3) * 2;

    auto issue = [&](int buf, int k0) {
        const uint32_t dbase = sbs + (uint32_t)buf * (PJ_STAGE * 2);
#pragma unroll
        for (int t = 0; t < 16; t++) {
            int cid = tid + t * 256;
            int tile = cid >> 10;
            int r = (cid >> 3) & 127;
            int c = cid & 7;
            const __nv_bfloat16* src;
            if (tile == 0)      src = g_aoh + (size_t)(m0 + r) * CE + k0 + c * 8;
            else if (tile == 1) src = g_aol + (size_t)(m0 + r) * CE + k0 + c * 8;
            else if (tile == 2) src = Wh_g + (size_t)(n0 + r) * CK + k0 + c * 8;
            else                src = Wl_g + (size_t)(n0 + r) * CK + k0 + c * 8;
            cpa16(dbase + (uint32_t)(tile * TSZ + r * GP + c * 8) * 2, src);
        }
        asm volatile("cp.async.commit_group;");
    };

    float acc[4][4][4];
#pragma unroll
    for (int a = 0; a < 4; a++)
#pragma unroll
        for (int b = 0; b < 4; b++)
#pragma unroll
            for (int c = 0; c < 4; c++) acc[a][b][c] = 0.f;

    issue(0, 0);
    for (int blk = 0; blk < 8; blk++) {
        const int buf = blk & 1;
        if (blk < 7) issue(buf ^ 1, (blk + 1) * 64);
        if (blk < 7) asm volatile("cp.async.wait_group 1;");
        else         asm volatile("cp.async.wait_group 0;");
        __syncthreads();

        const __nv_bfloat16* Ah = fs + buf * PJ_STAGE;
        const __nv_bfloat16* Al = Ah + TSZ;
        const __nv_bfloat16* Wh = Ah + 2 * TSZ;
        const __nv_bfloat16* Wl = Ah + 3 * TSZ;

#pragma unroll
        for (int ks = 0; ks < 4; ks++) {
            uint32_t ah[4][4], al[4][4];
#pragma unroll
            for (int mt = 0; mt < 4; mt++) {
                const __nv_bfloat16* ar = Ah + (wm * 64 + mt * 16 + lq) * GP + ks * 16 + lk;
                ah[mt][0] = *(const uint32_t*)ar;
                ah[mt][1] = *(const uint32_t*)(ar + 8 * GP);
                ah[mt][2] = *(const uint32_t*)(ar + 8);
                ah[mt][3] = *(const uint32_t*)(ar + 8 * GP + 8);
                const __nv_bfloat16* al_ = Al + (wm * 64 + mt * 16 + lq) * GP + ks * 16 + lk;
                al[mt][0] = *(const uint32_t*)al_;
                al[mt][1] = *(const uint32_t*)(al_ + 8 * GP);
                al[mt][2] = *(const uint32_t*)(al_ + 8);
                al[mt][3] = *(const uint32_t*)(al_ + 8 * GP + 8);
            }
#pragma unroll
            for (int nt = 0; nt < 4; nt++) {
                const __nv_bfloat16* bh = Wh + (wn * 32 + nt * 8 + lq) * GP + ks * 16 + lk;
                uint32_t bh0 = *(const uint32_t*)bh;
                uint32_t bh1 = *(const uint32_t*)(bh + 8);
                const __nv_bfloat16* bl = Wl + (wn * 32 + nt * 8 + lq) * GP + ks * 16 + lk;
                uint32_t bl0 = *(const uint32_t*)bl;
                uint32_t bl1 = *(const uint32_t*)(bl + 8);
#pragma unroll
                for (int mt = 0; mt < 4; mt++) {
                    mma16816(acc[mt][nt], ah[mt][0], ah[mt][1], ah[mt][2], ah[mt][3], bh0, bh1);
                    mma16816(acc[mt][nt], ah[mt][0], ah[mt][1], ah[mt][2], ah[mt][3], bl0, bl1);
                    mma16816(acc[mt][nt], al[mt][0], al[mt][1], al[mt][2], al[mt][3], bh0, bh1);
                }
            }
        }
        __syncthreads();
    }

#pragma unroll
    for (int mt = 0; mt < 4; mt++) {
#pragma unroll
        for (int nt = 0; nt < 4; nt++) {
            int row = m0 + wm * 64 + mt * 16 + lq;
            int col = n0 + wn * 32 + nt * 8 + lk;
            float b0 = bias[col], b1 = bias[col + 1];
#pragma unroll
            for (int half = 0; half < 2; half++) {
                int r = row + half * 8;
                float2 v;
                v.x = acc[mt][nt][half * 2 + 0] + b0;
                v.y = acc[mt][nt][half * 2 + 1] + b1;
                *(float2*)(C + (size_t)r * CE + col) = v;
            }
        }
    }
}

// ---------------- per-row norms (merged q + k, no smem) ----------------
__global__ void __launch_bounds__(256) norm_all_kernel()
{
    int blk = blockIdx.x;
    int row = (blk & 8191) * 8 + (threadIdx.x >> 5);
    int lane = threadIdx.x & 31;
    if (blk < 8192) {
        const float* p = g_qh + (size_t)row * 64;
        float a = p[lane], b = p[lane + 32];
        float s = a * a + b * b;
#pragma unroll
        for (int o = 16; o; o >>= 1) s += __shfl_down_sync(0xffffffffu, s, o);
        if (lane == 0) g_ll[row] = s;
    } else {
        const float* p1 = g_k1h + (size_t)row * 64;
        const float* p2 = g_k2h + (size_t)row * 64;
        float x0 = p1[lane], x1 = p1[lane + 32];
        float y0 = p2[lane], y1 = p2[lane + 32];
        float svv = x0 * x0 + x1 * x1;
        float saa = y0 * y0 + y1 * y1;
        float sva = x0 * y0 + x1 * y1;
#pragma unroll
        for (int o = 16; o; o >>= 1) {
            svv += __shfl_down_sync(0xffffffffu, svv, o);
            saa += __shfl_down_sync(0xffffffffu, saa, o);
            sva += __shfl_down_sync(0xffffffffu, sva, o);
        }
        if (lane == 0) { g_vv[row] = svv; g_aa[row] = saa; g_va[row] = sva; }
    }
}

// ---------------- V sum + transpose -> bf16 hi/lo VT [bh][d][s] ----------------
__global__ void __launch_bounds__(256) prep_vt()
{
    __shared__ float tile[64 * 65];
    const int bh = blockIdx.y;
    const int s0 = blockIdx.x * 64;
    const int tid = threadIdx.x;
    const float* vp = g_vh + (size_t)(bh * 1024 + s0) * 64;
    const float* vp2 = g_v2 + (size_t)(bh * 1024 + s0) * 64;
#pragma unroll
    for (int u = 0; u < 4; u++) {
        int id = tid + u * 256;
        int r = id >> 4, c4 = (id & 15) * 4;
        float4 x = *(const float4*)(vp + r * 64 + c4);
        float4 y = *(const float4*)(vp2 + r * 64 + c4);
        tile[r * 65 + c4 + 0] = x.x + y.x;
        tile[r * 65 + c4 + 1] = x.y + y.y;
        tile[r * 65 + c4 + 2] = x.z + y.z;
        tile[r * 65 + c4 + 3] = x.w + y.w;
    }
    __syncthreads();
#pragma unroll
    for (int u = 0; u < 8; u++) {
        int id = tid + u * 256;
        int d = id >> 5, sp = id & 31;
        float x0 = tile[(2 * sp) * 65 + d];
        float x1 = tile[(2 * sp + 1) * 65 + d];
        size_t off = ((size_t)(bh * 64 + d) * 1024 + s0 + 2 * sp);
        *(uint32_t*)(g_vthb + off) = pk_hi(x0, x1);
        *(uint32_t*)(g_vtlb + off) = pk_lo(x0, x1);
    }
}

// =====================================================================
// flash_mma: R13 best version — 128 q-rows, 256 thr, double-buffered,
//            fixed-max softmax, ks-outer MMA loops
// =====================================================================
#define FK (64 * GP)
#define FL_SMEM_B (2 * 6 * FK * 2)

__global__ void __launch_bounds__(256) flash_mma()
{
    extern __shared__ __nv_bfloat16 fs[];
    const uint32_t sbs = smem_u32(fs);

    const int tid = threadIdx.x;
    const int wid = tid >> 5, lane = tid & 31;
    const int lq = lane >> 2;
    const int lk = (lane & 3) * 2;
    const int bh = blockIdx.y;
    const int l0 = blockIdx.x * 128;
    const int bhS = bh * 1024;

    uint32_t qh[4][4], ql[4][4];
    {
        const float* q0 = g_qh + (size_t)(bhS + l0 + wid * 16 + lq) * 64;
        const float* q8 = q0 + 8 * 64;
#pragma unroll
        for (int ks = 0; ks < 4; ks++) {
            float2 x00 = *(const float2*)(q0 + ks * 16 + lk);
            float2 x10 = *(const float2*)(q8 + ks * 16 + lk);
            float2 x01 = *(const float2*)(q0 + ks * 16 + lk + 8);
            float2 x11 = *(const float2*)(q8 + ks * 16 + lk + 8);
            qh[ks][0] = pk_hi(x00.x, x00.y); ql[ks][0] = pk_lo(x00.x, x00.y);
            qh[ks][1] = pk_hi(x10.x, x10.y); ql[ks][1] = pk_lo(x10.x, x10.y);
            qh[ks][2] = pk_hi(x01.x, x01.y); ql[ks][2] = pk_lo(x01.x, x01.y);
            qh[ks][3] = pk_hi(x11.x, x11.y); ql[ks][3] = pk_lo(x11.x, x11.y);
        }
    }
    const float ll0 = g_ll[bhS + l0 + wid * 16 + lq];
    const float ll1 = g_ll[bhS + l0 + wid * 16 + lq + 8];

    float ls0 = 0.f, ls1 = 0.f;
    float o[8][4];
#pragma unroll
    for (int dt = 0; dt < 8; dt++)
#pragma unroll
        for (int c = 0; c < 4; c++) o[dt][c] = 0.f;

    auto issue = [&](int buf, int s0) {
        const uint32_t dbase = sbs + (uint32_t)buf * (6 * FK * 2);
#pragma unroll
        for (int t = 0; t < 12; t++) {
            int cid = tid + t * 256;
            int tile = cid >> 9;
            int r = (cid >> 3) & 63;
            int c = cid & 7;
            const __nv_bfloat16* src;
            if (tile == 0)      src = g_k1hb + ((size_t)(bhS + s0 + r) * 64 + c * 8);
            else if (tile == 1) src = g_k1lb + ((size_t)(bhS + s0 + r) * 64 + c * 8);
            else if (tile == 2) src = g_k2hb + ((size_t)(bhS + s0 + r) * 64 + c * 8);
            else if (tile == 3) src = g_k2lb + ((size_t)(bhS + s0 + r) * 64 + c * 8);
            else if (tile == 4) src = g_vthb + ((size_t)(bh * 64 + r) * 1024 + s0 + c * 8);
            else                src = g_vtlb + ((size_t)(bh * 64 + r) * 1024 + s0 + c * 8);
            cpa16(dbase + (uint32_t)(tile * FK + r * GP + c * 8) * 2, src);
        }
        asm volatile("cp.async.commit_group;");
    };

    issue(0, 0);

    for (int it = 0; it < 16; it++) {
        const int buf = it & 1;
        const int s0 = it * 64;
        if (it < 15) issue(buf ^ 1, s0 + 64);
        if (it < 15) asm volatile("cp.async.wait_group 1;");
        else         asm volatile("cp.async.wait_group 0;");
        __syncthreads();

        const __nv_bfloat16* Kb  = fs + buf * (6 * FK);
        const __nv_bfloat16* K1h = Kb;
        const __nv_bfloat16* K1l = Kb + FK;
        const __nv_bfloat16* K2h = Kb + 2 * FK;
        const __nv_bfloat16* K2l = Kb + 3 * FK;
        const __nv_bfloat16* VTh = Kb + 4 * FK;
        const __nv_bfloat16* VTl = Kb + 5 * FK;

        float lv[8][4], la[8][4];
#pragma unroll
        for (int nt = 0; nt < 8; nt++)
#pragma unroll
            for (int c = 0; c < 4; c++) { lv[nt][c] = 0.f; la[nt][c] = 0.f; }

#pragma unroll
        for (int ks = 0; ks < 4; ks++) {
#pragma unroll
            for (int nt = 0; nt < 8; nt++) {
                const __nv_bfloat16* b1h = K1h + (nt * 8 + lq) * GP + ks * 16 + lk;
                uint32_t h0 = *(const uint32_t*)b1h;
                uint32_t h1 = *(const uint32_t*)(b1h + 8);
                const __nv_bfloat16* b1l = K1l + (nt * 8 + lq) * GP + ks * 16 + lk;
                uint32_t l0_ = *(const uint32_t*)b1l;
                uint32_t l1_ = *(const uint32_t*)(b1l + 8);
                mma16816(lv[nt], qh[ks][0], qh[ks][1], qh[ks][2], qh[ks][3], h0, h1);
                mma16816(lv[nt], qh[ks][0], qh[ks][1], qh[ks][2], qh[ks][3], l0_, l1_);
                mma16816(lv[nt], ql[ks][0], ql[ks][1], ql[ks][2], ql[ks][3], h0, h1);
                const __nv_bfloat16* b2h = K2h + (nt * 8 + lq) * GP + ks * 16 + lk;
                uint32_t g0 = *(const uint32_t*)b2h;
                uint32_t g1 = *(const uint32_t*)(b2h + 8);
                const __nv_bfloat16* b2l = K2l + (nt * 8 + lq) * GP + ks * 16 + lk;
                uint32_t e0 = *(const uint32_t*)b2l;
                uint32_t e1 = *(const uint32_t*)(b2l + 8);
                mma16816(la[nt], qh[ks][0], qh[ks][1], qh[ks][2], qh[ks][3], g0, g1);
                mma16816(la[nt], qh[ks][0], qh[ks][1], qh[ks][2], qh[ks][3], e0, e1);
                mma16816(la[nt], ql[ks][0], ql[ks][1], ql[ks][2], ql[ks][3], g0, g1);
            }
        }

        // gram-det -> p = exp(-sqrt(det)) (fixed max 0)
#pragma unroll
        for (int nt = 0; nt < 8; nt++) {
            float2 vv2 = *(const float2*)(g_vv + bhS + s0 + nt * 8 + lk);
            float2 aa2 = *(const float2*)(g_aa + bhS + s0 + nt * 8 + lk);
            float2 va2 = *(const float2*)(g_va + bhS + s0 + nt * 8 + lk);
            float g2x = vv2.x * aa2.x - va2.x * va2.x;
            float g2y = vv2.y * aa2.y - va2.y * va2.y;
            {
                float LV = lv[nt][0], LA = la[nt][0];
                float det = ll0 * g2x - LV * (LV * aa2.x - LA * va2.x) + LA * (LV * va2.x - LA * vv2.x);
                float p = pexp_negsqrt(det);
                lv[nt][0] = p; ls0 += p;
            }
            {
                float LV = lv[nt][1], LA = la[nt][1];
                float det = ll0 * g2y - LV * (LV * aa2.y - LA * va2.y) + LA * (LV * va2.y - LA * vv2.y);
                float p = pexp_negsqrt(det);
                lv[nt][1] = p; ls0 += p;
            }
            {
                float LV = lv[nt][2], LA = la[nt][2];
                float det = ll1 * g2x - LV * (LV * aa2.x - LA * va2.x) + LA * (LV * va2.x - LA * vv2.x);
                float p = pexp_negsqrt(det);
                lv[nt][2] = p; ls1 += p;
            }
            {
                float LV = lv[nt][3], LA = la[nt][3];
                float det = ll1 * g2y - LV * (LV * aa2.y - LA * va2.y) + LA * (LV * va2.y - LA * vv2.y);
                float p = pexp_negsqrt(det);
                lv[nt][3] = p; ls1 += p;
            }
        }

        uint32_t ph[4][4], pl[4][4];
#pragma unroll
        for (int ks = 0; ks < 4; ks++) {
            ph[ks][0] = pk_hi(lv[2 * ks][0], lv[2 * ks][1]);
            pl[ks][0] = pk_lo(lv[2 * ks][0], lv[2 * ks][1]);
            ph[ks][1] = pk_hi(lv[2 * ks][2], lv[2 * ks][3]);
            pl[ks][1] = pk_lo(lv[2 * ks][2], lv[2 * ks][3]);
            ph[ks][2] = pk_hi(lv[2 * ks + 1][0], lv[2 * ks + 1][1]);
            pl[ks][2] = pk_lo(lv[2 * ks + 1][0], lv[2 * ks + 1][1]);
            ph[ks][3] = pk_hi(lv[2 * ks + 1][2], lv[2 * ks + 1][3]);
            pl[ks][3] = pk_lo(lv[2 * ks + 1][2], lv[2 * ks + 1][3]);
        }

#pragma unroll
        for (int ks = 0; ks < 4; ks++) {
#pragma unroll
            for (int dt = 0; dt < 8; dt++) {
                const __nv_bfloat16* vh = VTh + (dt * 8 + lq) * GP + ks * 16 + lk;
                uint32_t vh0 = *(const uint32_t*)vh;
                uint32_t vh1 = *(const uint32_t*)(vh + 8);
                const __nv_bfloat16* vl = VTl + (dt * 8 + lq) * GP + ks * 16 + lk;
                uint32_t vl0 = *(const uint32_t*)vl;
                uint32_t vl1 = *(const uint32_t*)(vl + 8);
                mma16816(o[dt], ph[ks][0], ph[ks][1], ph[ks][2], ph[ks][3], vh0, vh1);
                mma16816(o[dt], ph[ks][0], ph[ks][1], ph[ks][2], ph[ks][3], vl0, vl1);
                mma16816(o[dt], pl[ks][0], pl[ks][1], pl[ks][2], pl[ks][3], vh0, vh1);
            }
        }
        __syncthreads();
    }

    ls0 += __shfl_xor_sync(0xffffffffu, ls0, 1);
    ls0 += __shfl_xor_sync(0xffffffffu, ls0, 2);
    ls1 += __shfl_xor_sync(0xffffffffu, ls1, 1);
    ls1 += __shfl_xor_sync(0xffffffffu, ls1, 2);

    const float inv0 = frcp_pos(ls0);
    const float inv1 = frcp_pos(ls1);
    const int bi = bh >> 3, h = bh & 7;
    const int r0 = l0 + wid * 16 + lq;
#pragma unroll
    for (int dt = 0; dt < 8; dt++) {
        int d = dt * 8 + lk;
        float a0 = o[dt][0] * inv0, a1 = o[dt][1] * inv0;
        float b0 = o[dt][2] * inv1, b1 = o[dt][3] * inv1;
        size_t off0 = (size_t)(r0 * 8 + bi) * 512 + h * 64 + d;
        size_t off1 = (size_t)((r0 + 8) * 8 + bi) * 512 + h * 64 + d;
        *(uint32_t*)(g_aoh + off0) = pk_hi(a0, a1);
        *(uint32_t*)(g_aol + off0) = pk_lo(a0, a1);
        *(uint32_t*)(g_aoh + off1) = pk_hi(b0, b1);
        *(uint32_t*)(g_aol + off1) = pk_lo(b0, b1);
    }
}

// ---------------- launch ----------------
extern "C" void kernel_launch(void* const* d_in, const int* in_sizes, int n_in,
                              void* d_out, int out_size) {
    const float* query = (const float*)d_in[0];
    const float* mod1  = (const float*)d_in[1];
    const float* mod2  = (const float*)d_in[2];
    const float* Wq  = (const float*)d_in[3];  const float* bq  = (const float*)d_in[4];
    const float* Wk1 = (const float*)d_in[5];  const float* bk1 = (const float*)d_in[6];
    const float* Wk2 = (const float*)d_in[7];  const float* bk2 = (const float*)d_in[8];
    const float* Wv1 = (const float*)d_in[9];  const float* bv1 = (const float*)d_in[10];
    const float* Wv2 = (const float*)d_in[11]; const float* bv2 = (const float*)d_in[12];
    const float* Wg1 = (const float*)d_in[13]; const float* bg1 = (const float*)d_in[14];
    const float* Wg2 = (const float*)d_in[15]; const float* bg2 = (const float*)d_in[16];
    const float* Wo  = (const float*)d_in[17]; const float* bo  = (const float*)d_in[18];
    float* out = (float*)d_out;

    cudaFuncSetAttribute(proj_fused,  cudaFuncAttributeMaxDynamicSharedMemorySize, FUSED_SMEM_B);
    cudaFuncSetAttribute(proj_out_cp, cudaFuncAttributeMaxDynamicSharedMemorySize, PJ_SMEM_B);
    cudaFuncSetAttribute(flash_mma,   cudaFuncAttributeMaxDynamicSharedMemorySize, FL_SMEM_B);

    dim3 pb(256);
    prep_all<<<14336, pb>>>(query, mod1, mod2,
                            Wq, Wk1, Wk2, Wv1, Wv2, Wg1, Wg2, Wo);
    proj_fused<<<dim3(64, 4, 5), pb, FUSED_SMEM_B>>>(bq, bk1, bk2, bv1, bg1, bv2, bg2);
    norm_all_kernel<<<16384, pb>>>();
    prep_vt<<<dim3(16, 64), pb>>>();
    flash_mma<<<dim3(8, 64), 256, FL_SMEM_B>>>();
    proj_out_cp<<<dim3(64, 4), pb, PJ_SMEM_B>>>(bo, out);
}